// round 2
// baseline (speedup 1.0000x reference)
#include <cuda_runtime.h>
#include <math.h>

// ---------------------------------------------------------------------------
// RWKV-7 Tmix forward. B=4, T=2048, C=2048, H=32, N=64.
// Pipeline: token-shift mix -> projections (fused epilogues) -> WKV7 scan ->
//           groupnorm+bonus+gate -> output GEMM. All fp32.
// ---------------------------------------------------------------------------

#define BB 4
#define TT 2048
#define CC 2048
#define HH 32
#define NN 64
#define BT (BB*TT)                       // 8192
#define BTC ((size_t)BT*(size_t)CC)      // 16777216

// Scratch pool: 22 BTC-sized slots (~1.48 GB), static device memory.
__device__ float g_pool[22ull * 16777216ull];

// slot indices
#define SL_XR 0
#define SL_XW 1
#define SL_XK 2
#define SL_XV 3
#define SL_XA 4
#define SL_XG 5
#define SL_R  6
#define SL_K  7
#define SL_VL 8
#define SL_G  9
#define SL_WD 10
#define SL_A  11
#define SL_S  12
#define SL_RT 13
#define SL_WT 14
#define SL_KT 15
#define SL_VT 16
#define SL_AT 17
#define SL_BT 18
#define SL_Y  19
#define SL_Z  20
#define SL_SMALL 21

// ---------------------------------------------------------------------------
// Token-shift mixing: xx[t] = x[t-1]-x[t] (0 at t=0), x? = x + xx*maa_?
// ---------------------------------------------------------------------------
__global__ void mix_kernel(const float* __restrict__ x,
                           const float* __restrict__ mr, const float* __restrict__ mw,
                           const float* __restrict__ mk, const float* __restrict__ mv,
                           const float* __restrict__ ma, const float* __restrict__ mg,
                           float* __restrict__ xr, float* __restrict__ xw,
                           float* __restrict__ xk, float* __restrict__ xv,
                           float* __restrict__ xa, float* __restrict__ xg)
{
    size_t i = (size_t)blockIdx.x * blockDim.x + threadIdx.x;   // float4 index
    size_t n4 = BTC / 4;
    if (i >= n4) return;
    size_t e = i * 4;
    int c  = (int)(e % CC);
    int bt = (int)(e / CC);
    int t  = bt % TT;

    float4 xc = ((const float4*)x)[i];
    float4 xp = make_float4(0.f, 0.f, 0.f, 0.f);
    if (t > 0) xp = ((const float4*)x)[i - CC/4];
    float4 xx = make_float4(xp.x-xc.x, xp.y-xc.y, xp.z-xc.z, xp.w-xc.w);

    int c4 = c / 4;
#define DOMIX(MV, OUT) { \
        float4 m = ((const float4*)MV)[c4]; \
        float4 o = make_float4(xc.x + xx.x*m.x, xc.y + xx.y*m.y, \
                               xc.z + xx.z*m.z, xc.w + xx.w*m.w); \
        ((float4*)OUT)[i] = o; }
    DOMIX(mr, xr); DOMIX(mw, xw); DOMIX(mk, xk);
    DOMIX(mv, xv); DOMIX(ma, xa); DOMIX(mg, xg);
#undef DOMIX
}

// ---------------------------------------------------------------------------
// Tiled SGEMM: C[M,N] = A[M,K] @ B[K,N], row-major, with fused epilogue.
// EPI: 0=none, 1=tanh, 2=sigmoid, 3=sigmoid(acc+bias[n]), 4=decay transform
// Requires M%BM==0, N%BN==0, K%BK==0 (true for all our shapes).
// ---------------------------------------------------------------------------
template<int BM, int BN, int BK, int TM, int TN, int EPI>
__global__ void __launch_bounds__((BM/TM)*(BN/TN))
sgemm(const float* __restrict__ A, const float* __restrict__ B,
      float* __restrict__ C, int M, int N, int K, const float* __restrict__ bias)
{
    constexpr int THREADS = (BM/TM)*(BN/TN);
    __shared__ __align__(16) float As[BK][BM];
    __shared__ __align__(16) float Bs[BK][BN];

    const int tid  = threadIdx.x;
    const int tcol = tid % (BN/TN);
    const int trow = tid / (BN/TN);
    const int m0 = blockIdx.y * BM;
    const int n0 = blockIdx.x * BN;

    float acc[TM][TN];
#pragma unroll
    for (int i = 0; i < TM; i++)
#pragma unroll
        for (int j = 0; j < TN; j++) acc[i][j] = 0.f;

    for (int k0 = 0; k0 < K; k0 += BK) {
        // A tile (transposed into As[k][m])
#pragma unroll
        for (int i = tid; i < BM*(BK/4); i += THREADS) {
            int row = i / (BK/4);
            int k4  = i % (BK/4);
            float4 v = *(const float4*)(A + (size_t)(m0+row)*K + k0 + k4*4);
            As[k4*4+0][row] = v.x; As[k4*4+1][row] = v.y;
            As[k4*4+2][row] = v.z; As[k4*4+3][row] = v.w;
        }
        // B tile
#pragma unroll
        for (int i = tid; i < BK*(BN/4); i += THREADS) {
            int row = i / (BN/4);
            int nn4 = i % (BN/4);
            *(float4*)(&Bs[row][nn4*4]) =
                *(const float4*)(B + (size_t)(k0+row)*N + n0 + nn4*4);
        }
        __syncthreads();
#pragma unroll
        for (int kk = 0; kk < BK; kk++) {
            float ar[TM], br[TN];
#pragma unroll
            for (int i = 0; i < TM; i++) ar[i] = As[kk][trow*TM + i];
#pragma unroll
            for (int j = 0; j < TN; j++) br[j] = Bs[kk][tcol*TN + j];
#pragma unroll
            for (int i = 0; i < TM; i++)
#pragma unroll
                for (int j = 0; j < TN; j++)
                    acc[i][j] = fmaf(ar[i], br[j], acc[i][j]);
        }
        __syncthreads();
    }

#pragma unroll
    for (int i = 0; i < TM; i++) {
        int m = m0 + trow*TM + i;
#pragma unroll
        for (int j = 0; j < TN; j++) {
            int n = n0 + tcol*TN + j;
            float v = acc[i][j];
            if (EPI == 1) {
                v = tanhf(v);
            } else if (EPI == 2) {
                v = 1.f / (1.f + expf(-v));
            } else if (EPI == 3) {
                v += bias[n];
                v = 1.f / (1.f + expf(-v));
            } else if (EPI == 4) {
                // z = acc + decay[n]; w = -softplus(-z) - 0.5; store exp(-exp(w))
                float z  = v + bias[n];
                float sp = (z < -20.f) ? (-z) : log1pf(expf(-z));
                float w  = -sp - 0.5f;
                v = expf(-expf(w));
            }
            C[(size_t)m*N + n] = v;
        }
    }
}

// ---------------------------------------------------------------------------
// warp sum helper
// ---------------------------------------------------------------------------
__device__ __forceinline__ float warp_sum(float v) {
#pragma unroll
    for (int o = 16; o > 0; o >>= 1) v += __shfl_xor_sync(0xffffffffu, v, o);
    return v;
}

// ---------------------------------------------------------------------------
// Prep: value-residual mix, kk normalize, k adjust, transpose to [B*H, T, N].
// One warp per (bt, h) head-row; each lane handles n=lane and n=lane+32.
// ---------------------------------------------------------------------------
__global__ void prep_kernel(const float* __restrict__ r,  const float* __restrict__ wd,
                            const float* __restrict__ k,  const float* __restrict__ a,
                            const float* __restrict__ vl, const float* __restrict__ s,
                            const float* __restrict__ v0,
                            const float* __restrict__ misc_kkk,
                            const float* __restrict__ misc_a,
                            float* __restrict__ rT, float* __restrict__ wT,
                            float* __restrict__ kT, float* __restrict__ vT,
                            float* __restrict__ aT, float* __restrict__ bT)
{
    int gw   = (blockIdx.x * blockDim.x + threadIdx.x) >> 5;
    int lane = threadIdx.x & 31;
    if (gw >= BT * HH) return;
    int h  = gw % HH;
    int bt = gw / HH;
    int b  = bt / TT, t = bt % TT;

    size_t src = (size_t)bt * CC + (size_t)h * NN;
    size_t dst = (((size_t)(b*HH + h)) * TT + t) * NN;
    int n0 = lane, n1 = lane + 32;
    int c0 = h*NN + n0, c1 = h*NN + n1;

    float k0 = k[src+n0], k1 = k[src+n1];
    float kk0 = k0 * misc_kkk[c0], kk1 = k1 * misc_kkk[c1];
    float ssq = warp_sum(kk0*kk0 + kk1*kk1);
    float inv = 1.f / fmaxf(sqrtf(ssq), 1e-12f);
    kk0 *= inv; kk1 *= inv;

    float a0 = a[src+n0], a1 = a[src+n1];
    float vv0 = vl[src+n0], vv1 = vl[src+n1];
    float s0 = s[src+n0], s1 = s[src+n1];
    float fv0 = vv0 + (v0[src+n0] - vv0) * s0;
    float fv1 = vv1 + (v0[src+n1] - vv1) * s1;
    float fk0 = k0 * (1.f + (a0 - 1.f) * misc_a[c0]);
    float fk1 = k1 * (1.f + (a1 - 1.f) * misc_a[c1]);

    rT[dst+n0] = r[src+n0];  rT[dst+n1] = r[src+n1];
    wT[dst+n0] = wd[src+n0]; wT[dst+n1] = wd[src+n1];
    kT[dst+n0] = fk0;        kT[dst+n1] = fk1;
    vT[dst+n0] = fv0;        vT[dst+n1] = fv1;
    aT[dst+n0] = -kk0;       aT[dst+n1] = -kk1;
    bT[dst+n0] = kk0*a0;     bT[dst+n1] = kk1*a1;
}

// ---------------------------------------------------------------------------
// WKV7 recurrence. One block per (b,h), 64 threads; thread i owns state row i
// (64 fp32 registers). Double-buffered shared staging of per-step operands.
//   sa_i = sum_j S[i][j]*a[j]
//   S[i][j] = S[i][j]*w[j] + sa_i*b[j] + v_i*k[j]
//   y_i = sum_j S[i][j]*r[j]
// ---------------------------------------------------------------------------
__global__ void __launch_bounds__(64)
wkv7_kernel(const float* __restrict__ rT, const float* __restrict__ wT,
            const float* __restrict__ kT, const float* __restrict__ vT,
            const float* __restrict__ aT, const float* __restrict__ bT,
            float* __restrict__ yT)
{
    __shared__ __align__(16) float sb[2][6][NN];
    const int bh  = blockIdx.x;
    const int tid = threadIdx.x;   // 0..63
    const size_t base = (size_t)bh * TT * NN + tid;

    float st[NN];
#pragma unroll
    for (int j = 0; j < NN; j++) st[j] = 0.f;

    // preload t=0
    sb[0][0][tid] = rT[base]; sb[0][1][tid] = wT[base]; sb[0][2][tid] = kT[base];
    sb[0][3][tid] = vT[base]; sb[0][4][tid] = aT[base]; sb[0][5][tid] = bT[base];
    __syncthreads();

    int cur = 0;
    for (int t = 0; t < TT; t++) {
        float pr=0.f, pw=0.f, pk=0.f, pv=0.f, pa=0.f, pb=0.f;
        if (t + 1 < TT) {
            size_t b2 = base + (size_t)(t+1) * NN;
            pr = rT[b2]; pw = wT[b2]; pk = kT[b2];
            pv = vT[b2]; pa = aT[b2]; pb = bT[b2];
        }

        const float4* sr4 = (const float4*)sb[cur][0];
        const float4* sw4 = (const float4*)sb[cur][1];
        const float4* sk4 = (const float4*)sb[cur][2];
        const float4* sa4 = (const float4*)sb[cur][4];
        const float4* sbb4 = (const float4*)sb[cur][5];
        const float vi = sb[cur][3][tid];

        // sa_i = S[i] . a
        float c0=0.f, c1=0.f, c2=0.f, c3=0.f;
#pragma unroll
        for (int q = 0; q < NN/4; q++) {
            float4 a4 = sa4[q];
            c0 = fmaf(st[q*4+0], a4.x, c0);
            c1 = fmaf(st[q*4+1], a4.y, c1);
            c2 = fmaf(st[q*4+2], a4.z, c2);
            c3 = fmaf(st[q*4+3], a4.w, c3);
        }
        float sai = (c0 + c1) + (c2 + c3);

        // state update + y
        float y0=0.f, y1=0.f, y2=0.f, y3=0.f;
#pragma unroll
        for (int q = 0; q < NN/4; q++) {
            float4 w4 = sw4[q], b4 = sbb4[q], k4 = sk4[q], r4 = sr4[q];
            float t0 = fmaf(sai, b4.x, fmaf(vi, k4.x, st[q*4+0]*w4.x));
            float t1 = fmaf(sai, b4.y, fmaf(vi, k4.y, st[q*4+1]*w4.y));
            float t2 = fmaf(sai, b4.z, fmaf(vi, k4.z, st[q*4+2]*w4.z));
            float t3 = fmaf(sai, b4.w, fmaf(vi, k4.w, st[q*4+3]*w4.w));
            st[q*4+0] = t0; st[q*4+1] = t1; st[q*4+2] = t2; st[q*4+3] = t3;
            y0 = fmaf(t0, r4.x, y0);
            y1 = fmaf(t1, r4.y, y1);
            y2 = fmaf(t2, r4.z, y2);
            y3 = fmaf(t3, r4.w, y3);
        }
        yT[base + (size_t)t * NN] = (y0 + y1) + (y2 + y3);

        int nxt = cur ^ 1;
        if (t + 1 < TT) {
            sb[nxt][0][tid] = pr; sb[nxt][1][tid] = pw; sb[nxt][2][tid] = pk;
            sb[nxt][3][tid] = pv; sb[nxt][4][tid] = pa; sb[nxt][5][tid] = pb;
        }
        __syncthreads();
        cur = nxt;
    }
}

// ---------------------------------------------------------------------------
// GroupNorm + bonus + gate. One warp per (bt,h). z written in [B,T,C] layout.
// ---------------------------------------------------------------------------
__global__ void post_kernel(const float* __restrict__ yT, const float* __restrict__ rT,
                            const float* __restrict__ kT, const float* __restrict__ vT,
                            const float* __restrict__ g,  const float* __restrict__ faaaa,
                            const float* __restrict__ lnw, const float* __restrict__ lnb,
                            float* __restrict__ z)
{
    int gw   = (blockIdx.x * blockDim.x + threadIdx.x) >> 5;
    int lane = threadIdx.x & 31;
    if (gw >= BT * HH) return;
    int h  = gw % HH;
    int bt = gw / HH;
    int b  = bt / TT, t = bt % TT;

    size_t src = (size_t)bt * CC + (size_t)h * NN;
    size_t dst = (((size_t)(b*HH + h)) * TT + t) * NN;
    int n0 = lane, n1 = lane + 32;
    int c0 = h*NN + n0, c1 = h*NN + n1;

    float y0 = yT[dst+n0], y1 = yT[dst+n1];
    float sum = warp_sum(y0 + y1);
    float sq  = warp_sum(y0*y0 + y1*y1);
    float mu  = sum * (1.f/64.f);
    float var = sq * (1.f/64.f) - mu*mu;
    float rs  = rsqrtf(var + 6.4e-4f);   // 1e-5 * 64

    float rk = rT[dst+n0]*kT[dst+n0]*faaaa[c0]
             + rT[dst+n1]*kT[dst+n1]*faaaa[c1];
    float srk = warp_sum(rk);

    float z0 = ((y0 - mu)*rs*lnw[c0] + lnb[c0] + srk*vT[dst+n0]) * g[src+n0];
    float z1 = ((y1 - mu)*rs*lnw[c1] + lnb[c1] + srk*vT[dst+n1]) * g[src+n1];
    z[src+n0] = z0;
    z[src+n1] = z1;
}

__global__ void copy4_kernel(const float* __restrict__ src, float* __restrict__ dst,
                             size_t n4)
{
    size_t i = (size_t)blockIdx.x * blockDim.x + threadIdx.x;
    if (i < n4) ((float4*)dst)[i] = ((const float4*)src)[i];
}

// ---------------------------------------------------------------------------
// launch
// ---------------------------------------------------------------------------
extern "C" void kernel_launch(void* const* d_in, const int* in_sizes, int n_in,
                              void* d_out, int out_size)
{
    const float* x         = (const float*)d_in[0];
    const float* v0        = (const float*)d_in[1];
    const float* maa_r     = (const float*)d_in[2];
    const float* maa_w     = (const float*)d_in[3];
    const float* maa_k     = (const float*)d_in[4];
    const float* maa_v     = (const float*)d_in[5];
    const float* maa_a     = (const float*)d_in[6];
    const float* maa_g     = (const float*)d_in[7];
    const float* time_decay= (const float*)d_in[8];
    const float* faaaa     = (const float*)d_in[9];
    const float* time_aaaaa= (const float*)d_in[10];
    const float* td_w1     = (const float*)d_in[11];
    const float* td_w2     = (const float*)d_in[12];
    const float* aaa_w1    = (const float*)d_in[13];
    const float* aaa_w2    = (const float*)d_in[14];
    const float* gate_w1   = (const float*)d_in[15];
    const float* gate_w2   = (const float*)d_in[16];
    const float* mv_w1     = (const float*)d_in[17];
    const float* mv_w2     = (const float*)d_in[18];
    const float* misc_v    = (const float*)d_in[19];
    const float* misc_kkk  = (const float*)d_in[20];
    const float* misc_a    = (const float*)d_in[21];
    const float* Wr        = (const float*)d_in[22];
    const float* Wk        = (const float*)d_in[23];
    const float* Wv        = (const float*)d_in[24];
    const float* Wo        = (const float*)d_in[25];
    const float* ln_w      = (const float*)d_in[26];
    const float* ln_b      = (const float*)d_in[27];

    float* pool = nullptr;
    cudaGetSymbolAddress((void**)&pool, g_pool);

    float* xr = pool + (size_t)SL_XR * BTC;
    float* xw = pool + (size_t)SL_XW * BTC;
    float* xk = pool + (size_t)SL_XK * BTC;
    float* xv = pool + (size_t)SL_XV * BTC;
    float* xa = pool + (size_t)SL_XA * BTC;
    float* xg = pool + (size_t)SL_XG * BTC;
    float* r_ = pool + (size_t)SL_R  * BTC;
    float* k_ = pool + (size_t)SL_K  * BTC;
    float* vl = pool + (size_t)SL_VL * BTC;
    float* g_ = pool + (size_t)SL_G  * BTC;
    float* wd = pool + (size_t)SL_WD * BTC;
    float* a_ = pool + (size_t)SL_A  * BTC;
    float* s_ = pool + (size_t)SL_S  * BTC;
    float* rT = pool + (size_t)SL_RT * BTC;
    float* wT = pool + (size_t)SL_WT * BTC;
    float* kT = pool + (size_t)SL_KT * BTC;
    float* vT = pool + (size_t)SL_VT * BTC;
    float* aT = pool + (size_t)SL_AT * BTC;
    float* bT = pool + (size_t)SL_BT * BTC;
    float* yT = pool + (size_t)SL_Y  * BTC;
    float* z_ = pool + (size_t)SL_Z  * BTC;
    float* h_td   = pool + (size_t)SL_SMALL * BTC;
    float* h_aaa  = h_td  + (size_t)BT * 64;
    float* h_gate = h_aaa + (size_t)BT * 64;
    float* h_mv   = h_gate + (size_t)BT * 128;

    // 1. token-shift mixing
    {
        size_t n4 = BTC / 4;
        mix_kernel<<<(unsigned)((n4 + 255) / 256), 256>>>(
            x, maa_r, maa_w, maa_k, maa_v, maa_a, maa_g,
            xr, xw, xk, xv, xa, xg);
    }

    dim3 gBig(CC/128, BT/128);   // (16, 64)
    dim3 gSm(1, BT/64);          // (1, 128)

    // 2. big projections
    sgemm<128,128,16,8,8,0><<<gBig,256>>>(xr, Wr, r_, BT, CC, CC, nullptr);
    sgemm<128,128,16,8,8,0><<<gBig,256>>>(xk, Wk, k_, BT, CC, CC, nullptr);
    sgemm<128,128,16,8,8,0><<<gBig,256>>>(xv, Wv, vl, BT, CC, CC, nullptr);

    // 3. LoRA-style branches (stage1 small-N, stage2 fused epilogue)
    sgemm<64,64,16,4,4,1><<<gSm,256>>>(xw, td_w1, h_td, BT, 64, CC, nullptr);       // tanh
    sgemm<128,128,16,8,8,4><<<gBig,256>>>(h_td, td_w2, wd, BT, CC, 64, time_decay); // -> exp(-exp(w))
    sgemm<64,64,16,4,4,0><<<gSm,256>>>(xa, aaa_w1, h_aaa, BT, 64, CC, nullptr);
    sgemm<128,128,16,8,8,3><<<gBig,256>>>(h_aaa, aaa_w2, a_, BT, CC, 64, time_aaaaa);
    sgemm<64,128,16,4,8,2><<<gSm,256>>>(xg, gate_w1, h_gate, BT, 128, CC, nullptr); // sigmoid
    sgemm<128,128,16,8,8,0><<<gBig,256>>>(h_gate, gate_w2, g_, BT, CC, 128, nullptr);
    sgemm<64,32,16,4,2,0><<<gSm,256>>>(xv, mv_w1, h_mv, BT, 32, CC, nullptr);
    sgemm<128,128,16,8,8,3><<<gBig,256>>>(h_mv, mv_w2, s_, BT, CC, 32, misc_v);

    // 4. prep + transpose to head-major
    {
        int warps = BT * HH;                 // 262144
        prep_kernel<<<warps/8, 256>>>(r_, wd, k_, a_, vl, s_, v0,
                                      misc_kkk, misc_a,
                                      rT, wT, kT, vT, aT, bT);
    }

    // 5. WKV7 recurrence
    wkv7_kernel<<<BB*HH, 64>>>(rT, wT, kT, vT, aT, bT, yT);

    // 6. groupnorm + bonus + gate
    {
        int warps = BT * HH;
        post_kernel<<<warps/8, 256>>>(yT, rT, kT, vT, g_, faaaa, ln_w, ln_b, z_);
    }

    // 7. output projection directly into d_out
    sgemm<128,128,16,8,8,0><<<gBig,256>>>(z_, Wo, (float*)d_out, BT, CC, CC, nullptr);

    // 8. second output: v0 passthrough (if out buffer holds the tuple)
    if ((size_t)out_size >= 2 * BTC) {
        size_t n4 = BTC / 4;
        copy4_kernel<<<(unsigned)((n4 + 255) / 256), 256>>>(
            v0, (float*)d_out + BTC, n4);
    }
}

// round 4
// speedup vs baseline: 1.7864x; 1.7864x over previous
#include <cuda_runtime.h>
#include <cuda_bf16.h>
#include <math.h>
#include <stdint.h>

// ---------------------------------------------------------------------------
// RWKV-7 Tmix forward. B=4, T=2048, C=2048, H=32, N=64.
// R4: all large GEMMs on tensor cores via mma.sync.m16n8k16 bf16 with hi/lo
// split (3-MMA emulation, fp32 accum). tcgen05 unavailable (compute_103 PTX
// target). Stage-1 LoRA GEMMs stay SIMT fp32.
// ---------------------------------------------------------------------------

#define BB 4
#define TT 2048
#define CC 2048
#define HH 32
#define NN 64
#define BT (BB*TT)                       // 8192
#define BTC ((size_t)BT*(size_t)CC)      // 16777216

// Scratch pool: 24 BTC-sized fp32 slots (~1.54 GB).
__device__ float g_pool[24ull * 16777216ull];

#define SL_XR 0
#define SL_XW 1
#define SL_XK 2
#define SL_XV 3
#define SL_XA 4
#define SL_XG 5
#define SL_R  6
#define SL_K  7
#define SL_VL 8
#define SL_G  9
#define SL_WD 10
#define SL_A  11
#define SL_S  12
#define SL_RT 13
#define SL_WT 14
#define SL_KT 15
#define SL_VT 16
#define SL_AT 17
#define SL_BT 18
#define SL_Y  19
#define SL_Z  20
#define SL_SMALL 21
#define SL_WB  22   // big weight bf16 splits: 8 x (2048*2048) bf16
#define SL_AB  23   // activation bf16 splits: Ah, Al (8192*2048 bf16 each)

// ===========================================================================
// helpers
// ===========================================================================
__device__ __forceinline__ uint32_t smem_u32(const void* p) {
    uint32_t a;
    asm("{ .reg .u64 t; cvta.to.shared.u64 t, %1; cvt.u32.u64 %0, t; }"
        : "=r"(a) : "l"(p));
    return a;
}
__device__ __forceinline__ void cpasync16(uint32_t dst, const void* src) {
    asm volatile("cp.async.cg.shared.global [%0], [%1], 16;" :: "r"(dst), "l"(src));
}
__device__ __forceinline__ void ldsm4(uint32_t* r, uint32_t addr) {
    asm volatile("ldmatrix.sync.aligned.m8n8.x4.shared.b16 {%0,%1,%2,%3}, [%4];"
        : "=r"(r[0]), "=r"(r[1]), "=r"(r[2]), "=r"(r[3]) : "r"(addr));
}
__device__ __forceinline__ void mma16816(float* d, const uint32_t* a, const uint32_t* b) {
    asm volatile(
        "mma.sync.aligned.m16n8k16.row.col.f32.bf16.bf16.f32 "
        "{%0,%1,%2,%3}, {%4,%5,%6,%7}, {%8,%9}, {%0,%1,%2,%3};"
        : "+f"(d[0]), "+f"(d[1]), "+f"(d[2]), "+f"(d[3])
        : "r"(a[0]), "r"(a[1]), "r"(a[2]), "r"(a[3]), "r"(b[0]), "r"(b[1]));
}
__device__ __forceinline__ uint32_t pack_bf2(float a, float b) {
    __nv_bfloat162 t = __floats2bfloat162_rn(a, b);
    return *reinterpret_cast<uint32_t*>(&t);
}

// EPI: 0=none, 3=sigmoid(v+bias[n]), 4=decay transform with bias[n]
template<int EPI>
__device__ __forceinline__ float epi_apply(float v, float b) {
    if (EPI == 3) {
        return 1.f / (1.f + expf(-(v + b)));
    } else if (EPI == 4) {
        float z  = v + b;
        float sp = (z < -20.f) ? (-z) : log1pf(expf(-z));
        float w  = -sp - 0.5f;
        return expf(-expf(w));
    }
    return v;
}

// ===========================================================================
// Tensor-core GEMM: C[M,N] = A[M,K] @ B[K,N] with A given as (Ah+Al) bf16
// splits [M][K] and B as (Bh+Bl) bf16 splits stored transposed [N][K].
// D = Ah*Bh + Ah*Bl + Al*Bh, fp32 accumulate. CTA tile 128x128x32, 3-stage
// cp.async pipeline, warp tile 64x32 (2x4 warp grid). M,N,K multiples req'd.
// ===========================================================================
#define PADK 40                          // padded k extent (bf16) per row
#define TILE_B (128*PADK*2)              // 10240 bytes per operand tile
#define STG_B  (4*TILE_B)                // 40960 bytes per stage
#define HSTAGES 3
#define HSMEM  (HSTAGES*STG_B)           // 122880 bytes

template<int EPI>
__global__ void __launch_bounds__(256, 1)
hgemm(const __nv_bfloat16* __restrict__ Ah, const __nv_bfloat16* __restrict__ Al,
      const __nv_bfloat16* __restrict__ Bh, const __nv_bfloat16* __restrict__ Bl,
      float* __restrict__ C, int K, int Ntot, const float* __restrict__ bias)
{
    extern __shared__ char sm[];
    const int tid  = threadIdx.x;
    const int lane = tid & 31;
    const int wid  = tid >> 5;
    const int m0 = blockIdx.y * 128;
    const int n0 = blockIdx.x * 128;
    const int mw = (wid >> 2) * 64;      // warp m-offset (2 warps in m)
    const int nw = (wid & 3) * 32;       // warp n-offset (4 warps in n)
    const uint32_t sbase = smem_u32(sm);
    const int KT = K >> 5;

    float acc[4][4][4];
#pragma unroll
    for (int mt = 0; mt < 4; mt++)
#pragma unroll
        for (int nt = 0; nt < 4; nt++)
#pragma unroll
            for (int q = 0; q < 4; q++) acc[mt][nt][q] = 0.f;

    // --- async-load one 128x32 stage (4 operand tiles, 2048 x 16B chunks)
    auto issue = [&](int kt, int stage) {
        const int k0 = kt << 5;
        const uint32_t sdst = sbase + stage * STG_B;
#pragma unroll
        for (int u = 0; u < 8; u++) {
            int i  = tid + u * 256;
            int op = i >> 9;             // 0..3: Ah, Al, Bh, Bl
            int r  = (i & 511) >> 2;     // row 0..127
            int c  = i & 3;              // 16B chunk 0..3
            const __nv_bfloat16* src;
            if (op == 0)      src = Ah + (size_t)(m0 + r) * K + k0 + c * 8;
            else if (op == 1) src = Al + (size_t)(m0 + r) * K + k0 + c * 8;
            else if (op == 2) src = Bh + (size_t)(n0 + r) * K + k0 + c * 8;
            else              src = Bl + (size_t)(n0 + r) * K + k0 + c * 8;
            cpasync16(sdst + op * TILE_B + r * (PADK*2) + c * 16, src);
        }
    };

    // prologue: stages 0..HSTAGES-2
#pragma unroll
    for (int s = 0; s < HSTAGES - 1; s++) {
        if (s < KT) issue(s, s);
        asm volatile("cp.async.commit_group;" ::: "memory");
    }

    const int grp = lane >> 3;
    const int l7  = lane & 7;

    for (int kt = 0; kt < KT; kt++) {
        asm volatile("cp.async.wait_group 1;" ::: "memory");
        __syncthreads();

        const int st = kt % HSTAGES;
        const uint32_t sAh = sbase + st * STG_B;
        const uint32_t sAl = sAh + TILE_B;
        const uint32_t sBh = sAh + 2 * TILE_B;
        const uint32_t sBl = sAh + 3 * TILE_B;

#pragma unroll
        for (int kk = 0; kk < 2; kk++) {
            const int ko = kk * 16;
            uint32_t ahf[4][4], alf[4][4], bhf[4][2], blf[4][2];
            // A fragments: per m-tile, lanes address 8x8 b16 matrices
#pragma unroll
            for (int mt = 0; mt < 4; mt++) {
                int row = mw + mt * 16 + ((grp & 1) << 3) + l7;
                int kof = ko + ((grp & 2) << 2);
                uint32_t a = row * (PADK*2) + kof * 2;
                ldsm4(ahf[mt], sAh + a);
                ldsm4(alf[mt], sAl + a);
            }
            // B fragments: each x4 covers two n-tiles
#pragma unroll
            for (int np = 0; np < 2; np++) {
                int row = nw + np * 16 + ((grp >> 1) << 3) + l7;
                int kof = ko + ((grp & 1) << 3);
                uint32_t a = row * (PADK*2) + kof * 2;
                uint32_t t[4];
                ldsm4(t, sBh + a);
                bhf[np*2][0]   = t[0]; bhf[np*2][1]   = t[1];
                bhf[np*2+1][0] = t[2]; bhf[np*2+1][1] = t[3];
                ldsm4(t, sBl + a);
                blf[np*2][0]   = t[0]; blf[np*2][1]   = t[1];
                blf[np*2+1][0] = t[2]; blf[np*2+1][1] = t[3];
            }
#pragma unroll
            for (int mt = 0; mt < 4; mt++)
#pragma unroll
                for (int nt = 0; nt < 4; nt++) {
                    mma16816(acc[mt][nt], ahf[mt], bhf[nt]);
                    mma16816(acc[mt][nt], ahf[mt], blf[nt]);
                    mma16816(acc[mt][nt], alf[mt], bhf[nt]);
                }
        }

        int nkt = kt + HSTAGES - 1;
        if (nkt < KT) issue(nkt, nkt % HSTAGES);
        asm volatile("cp.async.commit_group;" ::: "memory");
    }

    // epilogue: direct global stores (float2), fused nonlinearity
    const int r0 = lane >> 2;
    const int c0 = (lane & 3) * 2;
#pragma unroll
    for (int mt = 0; mt < 4; mt++) {
#pragma unroll
        for (int nt = 0; nt < 4; nt++) {
            int row = m0 + mw + mt * 16 + r0;
            int col = n0 + nw + nt * 8 + c0;
            float b0 = 0.f, b1 = 0.f;
            if (EPI != 0) { b0 = bias[col]; b1 = bias[col + 1]; }
            float v0 = epi_apply<EPI>(acc[mt][nt][0], b0);
            float v1 = epi_apply<EPI>(acc[mt][nt][1], b1);
            float v2 = epi_apply<EPI>(acc[mt][nt][2], b0);
            float v3 = epi_apply<EPI>(acc[mt][nt][3], b1);
            *(float2*)(C + (size_t)row * Ntot + col)       = make_float2(v0, v1);
            *(float2*)(C + (size_t)(row + 8) * Ntot + col) = make_float2(v2, v3);
        }
    }
}

// ===========================================================================
// fp32 -> bf16 hi/lo split (elementwise, float4 vectorized)
// ===========================================================================
__global__ void split_kernel(const float* __restrict__ s,
                             __nv_bfloat16* __restrict__ hi,
                             __nv_bfloat16* __restrict__ lo, size_t n4)
{
    size_t i = (size_t)blockIdx.x * blockDim.x + threadIdx.x;
    if (i >= n4) return;
    float4 v = ((const float4*)s)[i];
    float hx = __bfloat162float(__float2bfloat16(v.x));
    float hy = __bfloat162float(__float2bfloat16(v.y));
    float hz = __bfloat162float(__float2bfloat16(v.z));
    float hw = __bfloat162float(__float2bfloat16(v.w));
    ((uint2*)hi)[i] = make_uint2(pack_bf2(v.x, v.y), pack_bf2(v.z, v.w));
    ((uint2*)lo)[i] = make_uint2(pack_bf2(v.x - hx, v.y - hy),
                                 pack_bf2(v.z - hz, v.w - hw));
}

// ===========================================================================
// Weight transpose + split: in W[K][N] fp32 -> out Th/Tl[N][K] bf16
// ===========================================================================
__global__ void transpose_split(const float* __restrict__ W,
                                __nv_bfloat16* __restrict__ Th,
                                __nv_bfloat16* __restrict__ Tl, int K, int N)
{
    __shared__ float tile[32][33];
    int bx = blockIdx.x * 32;   // n
    int by = blockIdx.y * 32;   // k
#pragma unroll
    for (int j = 0; j < 32; j += 8)
        tile[threadIdx.y + j][threadIdx.x] =
            W[(size_t)(by + threadIdx.y + j) * N + bx + threadIdx.x];
    __syncthreads();
#pragma unroll
    for (int j = 0; j < 32; j += 8) {
        float v = tile[threadIdx.x][threadIdx.y + j];
        int n = bx + threadIdx.y + j;
        int k = by + threadIdx.x;
        __nv_bfloat16 h = __float2bfloat16(v);
        Th[(size_t)n * K + k] = h;
        Tl[(size_t)n * K + k] = __float2bfloat16(v - __bfloat162float(h));
    }
}

// ---------------------------------------------------------------------------
// Token-shift mixing
// ---------------------------------------------------------------------------
__global__ void mix_kernel(const float* __restrict__ x,
                           const float* __restrict__ mr, const float* __restrict__ mw,
                           const float* __restrict__ mk, const float* __restrict__ mv,
                           const float* __restrict__ ma, const float* __restrict__ mg,
                           float* __restrict__ xr, float* __restrict__ xw,
                           float* __restrict__ xk, float* __restrict__ xv,
                           float* __restrict__ xa, float* __restrict__ xg)
{
    size_t i = (size_t)blockIdx.x * blockDim.x + threadIdx.x;
    size_t n4 = BTC / 4;
    if (i >= n4) return;
    size_t e = i * 4;
    int c  = (int)(e % CC);
    int bt = (int)(e / CC);
    int t  = bt % TT;

    float4 xc = ((const float4*)x)[i];
    float4 xp = make_float4(0.f, 0.f, 0.f, 0.f);
    if (t > 0) xp = ((const float4*)x)[i - CC/4];
    float4 xx = make_float4(xp.x-xc.x, xp.y-xc.y, xp.z-xc.z, xp.w-xc.w);

    int c4 = c / 4;
#define DOMIX(MV, OUT) { \
        float4 m = ((const float4*)MV)[c4]; \
        float4 o = make_float4(xc.x + xx.x*m.x, xc.y + xx.y*m.y, \
                               xc.z + xx.z*m.z, xc.w + xx.w*m.w); \
        ((float4*)OUT)[i] = o; }
    DOMIX(mr, xr); DOMIX(mw, xw); DOMIX(mk, xk);
    DOMIX(mv, xv); DOMIX(ma, xa); DOMIX(mg, xg);
#undef DOMIX
}

// ---------------------------------------------------------------------------
// SIMT SGEMM for stage-1 LoRA GEMMs (small N), fused epilogues.
// EPI: 0=none, 1=tanh, 2=sigmoid
// ---------------------------------------------------------------------------
template<int BM, int BN, int BK, int TM, int TN, int EPI>
__global__ void __launch_bounds__((BM/TM)*(BN/TN))
sgemm(const float* __restrict__ A, const float* __restrict__ B,
      float* __restrict__ C, int M, int N, int K, const float* __restrict__ bias)
{
    constexpr int THREADS = (BM/TM)*(BN/TN);
    __shared__ __align__(16) float As[BK][BM];
    __shared__ __align__(16) float Bs[BK][BN];

    const int tid  = threadIdx.x;
    const int tcol = tid % (BN/TN);
    const int trow = tid / (BN/TN);
    const int m0 = blockIdx.y * BM;
    const int n0 = blockIdx.x * BN;

    float acc[TM][TN];
#pragma unroll
    for (int i = 0; i < TM; i++)
#pragma unroll
        for (int j = 0; j < TN; j++) acc[i][j] = 0.f;

    for (int k0 = 0; k0 < K; k0 += BK) {
#pragma unroll
        for (int i = tid; i < BM*(BK/4); i += THREADS) {
            int row = i / (BK/4);
            int k4  = i % (BK/4);
            float4 v = *(const float4*)(A + (size_t)(m0+row)*K + k0 + k4*4);
            As[k4*4+0][row] = v.x; As[k4*4+1][row] = v.y;
            As[k4*4+2][row] = v.z; As[k4*4+3][row] = v.w;
        }
#pragma unroll
        for (int i = tid; i < BK*(BN/4); i += THREADS) {
            int row = i / (BN/4);
            int nn4 = i % (BN/4);
            *(float4*)(&Bs[row][nn4*4]) =
                *(const float4*)(B + (size_t)(k0+row)*N + n0 + nn4*4);
        }
        __syncthreads();
#pragma unroll
        for (int kk = 0; kk < BK; kk++) {
            float ar[TM], br[TN];
#pragma unroll
            for (int i = 0; i < TM; i++) ar[i] = As[kk][trow*TM + i];
#pragma unroll
            for (int j = 0; j < TN; j++) br[j] = Bs[kk][tcol*TN + j];
#pragma unroll
            for (int i = 0; i < TM; i++)
#pragma unroll
                for (int j = 0; j < TN; j++)
                    acc[i][j] = fmaf(ar[i], br[j], acc[i][j]);
        }
        __syncthreads();
    }

#pragma unroll
    for (int i = 0; i < TM; i++) {
        int m = m0 + trow*TM + i;
#pragma unroll
        for (int j = 0; j < TN; j++) {
            int n = n0 + tcol*TN + j;
            float v = acc[i][j];
            if (EPI == 1)      v = tanhf(v);
            else if (EPI == 2) v = 1.f / (1.f + expf(-v));
            C[(size_t)m*N + n] = v;
        }
    }
}

// ---------------------------------------------------------------------------
__device__ __forceinline__ float warp_sum(float v) {
#pragma unroll
    for (int o = 16; o > 0; o >>= 1) v += __shfl_xor_sync(0xffffffffu, v, o);
    return v;
}

// ---------------------------------------------------------------------------
// Prep: value-residual mix, kk normalize, k adjust, transpose to [B*H, T, N].
// ---------------------------------------------------------------------------
__global__ void prep_kernel(const float* __restrict__ r,  const float* __restrict__ wd,
                            const float* __restrict__ k,  const float* __restrict__ a,
                            const float* __restrict__ vl, const float* __restrict__ s,
                            const float* __restrict__ v0,
                            const float* __restrict__ misc_kkk,
                            const float* __restrict__ misc_a,
                            float* __restrict__ rT, float* __restrict__ wT,
                            float* __restrict__ kT, float* __restrict__ vT,
                            float* __restrict__ aT, float* __restrict__ bT)
{
    int gw   = (blockIdx.x * blockDim.x + threadIdx.x) >> 5;
    int lane = threadIdx.x & 31;
    if (gw >= BT * HH) return;
    int h  = gw % HH;
    int bt = gw / HH;
    int b  = bt / TT, t = bt % TT;

    size_t src = (size_t)bt * CC + (size_t)h * NN;
    size_t dst = (((size_t)(b*HH + h)) * TT + t) * NN;
    int n0 = lane, n1 = lane + 32;
    int c0 = h*NN + n0, c1 = h*NN + n1;

    float k0 = k[src+n0], k1 = k[src+n1];
    float kk0 = k0 * misc_kkk[c0], kk1 = k1 * misc_kkk[c1];
    float ssq = warp_sum(kk0*kk0 + kk1*kk1);
    float inv = 1.f / fmaxf(sqrtf(ssq), 1e-12f);
    kk0 *= inv; kk1 *= inv;

    float a0 = a[src+n0], a1 = a[src+n1];
    float vv0 = vl[src+n0], vv1 = vl[src+n1];
    float s0 = s[src+n0], s1 = s[src+n1];
    float fv0 = vv0 + (v0[src+n0] - vv0) * s0;
    float fv1 = vv1 + (v0[src+n1] - vv1) * s1;
    float fk0 = k0 * (1.f + (a0 - 1.f) * misc_a[c0]);
    float fk1 = k1 * (1.f + (a1 - 1.f) * misc_a[c1]);

    rT[dst+n0] = r[src+n0];  rT[dst+n1] = r[src+n1];
    wT[dst+n0] = wd[src+n0]; wT[dst+n1] = wd[src+n1];
    kT[dst+n0] = fk0;        kT[dst+n1] = fk1;
    vT[dst+n0] = fv0;        vT[dst+n1] = fv1;
    aT[dst+n0] = -kk0;       aT[dst+n1] = -kk1;
    bT[dst+n0] = kk0*a0;     bT[dst+n1] = kk1*a1;
}

// ---------------------------------------------------------------------------
// WKV7 recurrence. One block per (b,h), 64 threads; thread i owns state row i.
// ---------------------------------------------------------------------------
__global__ void __launch_bounds__(64)
wkv7_kernel(const float* __restrict__ rT, const float* __restrict__ wT,
            const float* __restrict__ kT, const float* __restrict__ vT,
            const float* __restrict__ aT, const float* __restrict__ bT,
            float* __restrict__ yT)
{
    __shared__ __align__(16) float sb[2][6][NN];
    const int bh  = blockIdx.x;
    const int tid = threadIdx.x;
    const size_t base = (size_t)bh * TT * NN + tid;

    float st[NN];
#pragma unroll
    for (int j = 0; j < NN; j++) st[j] = 0.f;

    sb[0][0][tid] = rT[base]; sb[0][1][tid] = wT[base]; sb[0][2][tid] = kT[base];
    sb[0][3][tid] = vT[base]; sb[0][4][tid] = aT[base]; sb[0][5][tid] = bT[base];
    __syncthreads();

    int cur = 0;
    for (int t = 0; t < TT; t++) {
        float pr=0.f, pw=0.f, pk=0.f, pv=0.f, pa=0.f, pb=0.f;
        if (t + 1 < TT) {
            size_t b2 = base + (size_t)(t+1) * NN;
            pr = rT[b2]; pw = wT[b2]; pk = kT[b2];
            pv = vT[b2]; pa = aT[b2]; pb = bT[b2];
        }

        const float4* sr4 = (const float4*)sb[cur][0];
        const float4* sw4 = (const float4*)sb[cur][1];
        const float4* sk4 = (const float4*)sb[cur][2];
        const float4* sa4 = (const float4*)sb[cur][4];
        const float4* sbb4 = (const float4*)sb[cur][5];
        const float vi = sb[cur][3][tid];

        float c0=0.f, c1=0.f, c2=0.f, c3=0.f;
#pragma unroll
        for (int q = 0; q < NN/4; q++) {
            float4 a4 = sa4[q];
            c0 = fmaf(st[q*4+0], a4.x, c0);
            c1 = fmaf(st[q*4+1], a4.y, c1);
            c2 = fmaf(st[q*4+2], a4.z, c2);
            c3 = fmaf(st[q*4+3], a4.w, c3);
        }
        float sai = (c0 + c1) + (c2 + c3);

        float y0=0.f, y1=0.f, y2=0.f, y3=0.f;
#pragma unroll
        for (int q = 0; q < NN/4; q++) {
            float4 w4 = sw4[q], b4 = sbb4[q], k4 = sk4[q], r4 = sr4[q];
            float t0 = fmaf(sai, b4.x, fmaf(vi, k4.x, st[q*4+0]*w4.x));
            float t1 = fmaf(sai, b4.y, fmaf(vi, k4.y, st[q*4+1]*w4.y));
            float t2 = fmaf(sai, b4.z, fmaf(vi, k4.z, st[q*4+2]*w4.z));
            float t3 = fmaf(sai, b4.w, fmaf(vi, k4.w, st[q*4+3]*w4.w));
            st[q*4+0] = t0; st[q*4+1] = t1; st[q*4+2] = t2; st[q*4+3] = t3;
            y0 = fmaf(t0, r4.x, y0);
            y1 = fmaf(t1, r4.y, y1);
            y2 = fmaf(t2, r4.z, y2);
            y3 = fmaf(t3, r4.w, y3);
        }
        yT[base + (size_t)t * NN] = (y0 + y1) + (y2 + y3);

        int nxt = cur ^ 1;
        if (t + 1 < TT) {
            sb[nxt][0][tid] = pr; sb[nxt][1][tid] = pw; sb[nxt][2][tid] = pk;
            sb[nxt][3][tid] = pv; sb[nxt][4][tid] = pa; sb[nxt][5][tid] = pb;
        }
        __syncthreads();
        cur = nxt;
    }
}

// ---------------------------------------------------------------------------
// GroupNorm + bonus + gate
// ---------------------------------------------------------------------------
__global__ void post_kernel(const float* __restrict__ yT, const float* __restrict__ rT,
                            const float* __restrict__ kT, const float* __restrict__ vT,
                            const float* __restrict__ g,  const float* __restrict__ faaaa,
                            const float* __restrict__ lnw, const float* __restrict__ lnb,
                            float* __restrict__ z)
{
    int gw   = (blockIdx.x * blockDim.x + threadIdx.x) >> 5;
    int lane = threadIdx.x & 31;
    if (gw >= BT * HH) return;
    int h  = gw % HH;
    int bt = gw / HH;
    int b  = bt / TT, t = bt % TT;

    size_t src = (size_t)bt * CC + (size_t)h * NN;
    size_t dst = (((size_t)(b*HH + h)) * TT + t) * NN;
    int n0 = lane, n1 = lane + 32;
    int c0 = h*NN + n0, c1 = h*NN + n1;

    float y0 = yT[dst+n0], y1 = yT[dst+n1];
    float sum = warp_sum(y0 + y1);
    float sq  = warp_sum(y0*y0 + y1*y1);
    float mu  = sum * (1.f/64.f);
    float var = sq * (1.f/64.f) - mu*mu;
    float rs  = rsqrtf(var + 6.4e-4f);

    float rk = rT[dst+n0]*kT[dst+n0]*faaaa[c0]
             + rT[dst+n1]*kT[dst+n1]*faaaa[c1];
    float srk = warp_sum(rk);

    float z0 = ((y0 - mu)*rs*lnw[c0] + lnb[c0] + srk*vT[dst+n0]) * g[src+n0];
    float z1 = ((y1 - mu)*rs*lnw[c1] + lnb[c1] + srk*vT[dst+n1]) * g[src+n1];
    z[src+n0] = z0;
    z[src+n1] = z1;
}

__global__ void copy4_kernel(const float* __restrict__ src, float* __restrict__ dst,
                             size_t n4)
{
    size_t i = (size_t)blockIdx.x * blockDim.x + threadIdx.x;
    if (i < n4) ((float4*)dst)[i] = ((const float4*)src)[i];
}

// ---------------------------------------------------------------------------
// launch
// ---------------------------------------------------------------------------
extern "C" void kernel_launch(void* const* d_in, const int* in_sizes, int n_in,
                              void* d_out, int out_size)
{
    const float* x         = (const float*)d_in[0];
    const float* v0        = (const float*)d_in[1];
    const float* maa_r     = (const float*)d_in[2];
    const float* maa_w     = (const float*)d_in[3];
    const float* maa_k     = (const float*)d_in[4];
    const float* maa_v     = (const float*)d_in[5];
    const float* maa_a     = (const float*)d_in[6];
    const float* maa_g     = (const float*)d_in[7];
    const float* time_decay= (const float*)d_in[8];
    const float* faaaa     = (const float*)d_in[9];
    const float* time_aaaaa= (const float*)d_in[10];
    const float* td_w1     = (const float*)d_in[11];
    const float* td_w2     = (const float*)d_in[12];
    const float* aaa_w1    = (const float*)d_in[13];
    const float* aaa_w2    = (const float*)d_in[14];
    const float* gate_w1   = (const float*)d_in[15];
    const float* gate_w2   = (const float*)d_in[16];
    const float* mv_w1     = (const float*)d_in[17];
    const float* mv_w2     = (const float*)d_in[18];
    const float* misc_v    = (const float*)d_in[19];
    const float* misc_kkk  = (const float*)d_in[20];
    const float* misc_a    = (const float*)d_in[21];
    const float* Wr        = (const float*)d_in[22];
    const float* Wk        = (const float*)d_in[23];
    const float* Wv        = (const float*)d_in[24];
    const float* Wo        = (const float*)d_in[25];
    const float* ln_w      = (const float*)d_in[26];
    const float* ln_b      = (const float*)d_in[27];

    float* pool = nullptr;
    cudaGetSymbolAddress((void**)&pool, g_pool);

    float* xr = pool + (size_t)SL_XR * BTC;
    float* xw = pool + (size_t)SL_XW * BTC;
    float* xk = pool + (size_t)SL_XK * BTC;
    float* xv = pool + (size_t)SL_XV * BTC;
    float* xa = pool + (size_t)SL_XA * BTC;
    float* xg = pool + (size_t)SL_XG * BTC;
    float* r_ = pool + (size_t)SL_R  * BTC;
    float* k_ = pool + (size_t)SL_K  * BTC;
    float* vl = pool + (size_t)SL_VL * BTC;
    float* g_ = pool + (size_t)SL_G  * BTC;
    float* wd = pool + (size_t)SL_WD * BTC;
    float* a_ = pool + (size_t)SL_A  * BTC;
    float* s_ = pool + (size_t)SL_S  * BTC;
    float* rT = pool + (size_t)SL_RT * BTC;
    float* wT = pool + (size_t)SL_WT * BTC;
    float* kT = pool + (size_t)SL_KT * BTC;
    float* vT = pool + (size_t)SL_VT * BTC;
    float* aT = pool + (size_t)SL_AT * BTC;
    float* bT = pool + (size_t)SL_BT * BTC;
    float* yT = pool + (size_t)SL_Y  * BTC;
    float* z_ = pool + (size_t)SL_Z  * BTC;

    // small slot: stage-1 activations (fp32) + their splits + small weight T
    float* small = pool + (size_t)SL_SMALL * BTC;
    float* h_td   = small;                     // 8192*64
    float* h_aaa  = h_td   + (size_t)BT*64;
    float* h_gate = h_aaa  + (size_t)BT*64;    // 8192*128
    float* h_mv   = h_gate + (size_t)BT*128;   // 8192*32
    __nv_bfloat16* sb16 = (__nv_bfloat16*)(h_mv + (size_t)BT*32);
    __nv_bfloat16* td_h   = sb16;                         // BT*64
    __nv_bfloat16* td_l   = td_h   + (size_t)BT*64;
    __nv_bfloat16* aaa_h  = td_l   + (size_t)BT*64;
    __nv_bfloat16* aaa_l  = aaa_h  + (size_t)BT*64;
    __nv_bfloat16* gate_h = aaa_l  + (size_t)BT*64;       // BT*128
    __nv_bfloat16* gate_l = gate_h + (size_t)BT*128;
    __nv_bfloat16* mv_h   = gate_l + (size_t)BT*128;      // BT*32
    __nv_bfloat16* mv_l   = mv_h   + (size_t)BT*32;
    __nv_bfloat16* tdw_h  = mv_l   + (size_t)BT*32;       // 2048*64
    __nv_bfloat16* tdw_l  = tdw_h  + (size_t)2048*64;
    __nv_bfloat16* aaaw_h = tdw_l  + (size_t)2048*64;
    __nv_bfloat16* aaaw_l = aaaw_h + (size_t)2048*64;
    __nv_bfloat16* gatew_h= aaaw_l + (size_t)2048*64;     // 2048*128
    __nv_bfloat16* gatew_l= gatew_h+ (size_t)2048*128;
    __nv_bfloat16* mvw_h  = gatew_l+ (size_t)2048*128;    // 2048*32
    __nv_bfloat16* mvw_l  = mvw_h  + (size_t)2048*32;

    // big weight splits
    __nv_bfloat16* wb = (__nv_bfloat16*)(pool + (size_t)SL_WB * BTC);
    const size_t WSZ = (size_t)CC * CC;
    __nv_bfloat16* Wr_h = wb;            __nv_bfloat16* Wr_l = wb + WSZ;
    __nv_bfloat16* Wk_h = wb + 2*WSZ;    __nv_bfloat16* Wk_l = wb + 3*WSZ;
    __nv_bfloat16* Wv_h = wb + 4*WSZ;    __nv_bfloat16* Wv_l = wb + 5*WSZ;
    __nv_bfloat16* Wo_h = wb + 6*WSZ;    __nv_bfloat16* Wo_l = wb + 7*WSZ;

    // activation splits (reused per GEMM)
    __nv_bfloat16* Abh = (__nv_bfloat16*)(pool + (size_t)SL_AB * BTC);
    __nv_bfloat16* Abl = Abh + BTC;

    cudaFuncSetAttribute(hgemm<0>, cudaFuncAttributeMaxDynamicSharedMemorySize, HSMEM);
    cudaFuncSetAttribute(hgemm<3>, cudaFuncAttributeMaxDynamicSharedMemorySize, HSMEM);
    cudaFuncSetAttribute(hgemm<4>, cudaFuncAttributeMaxDynamicSharedMemorySize, HSMEM);

    dim3 tb(32, 8);
    // 0. weight transpose + split
    transpose_split<<<dim3(CC/32, CC/32), tb>>>(Wr, Wr_h, Wr_l, CC, CC);
    transpose_split<<<dim3(CC/32, CC/32), tb>>>(Wk, Wk_h, Wk_l, CC, CC);
    transpose_split<<<dim3(CC/32, CC/32), tb>>>(Wv, Wv_h, Wv_l, CC, CC);
    transpose_split<<<dim3(CC/32, CC/32), tb>>>(Wo, Wo_h, Wo_l, CC, CC);
    transpose_split<<<dim3(CC/32, 64/32),  tb>>>(td_w2,  tdw_h,  tdw_l,  64,  CC);
    transpose_split<<<dim3(CC/32, 64/32),  tb>>>(aaa_w2, aaaw_h, aaaw_l, 64,  CC);
    transpose_split<<<dim3(CC/32, 128/32), tb>>>(gate_w2,gatew_h,gatew_l,128, CC);
    transpose_split<<<dim3(CC/32, 32/32),  tb>>>(mv_w2,  mvw_h,  mvw_l,  32,  CC);

    // 1. token-shift mixing
    {
        size_t n4 = BTC / 4;
        mix_kernel<<<(unsigned)((n4 + 255) / 256), 256>>>(
            x, maa_r, maa_w, maa_k, maa_v, maa_a, maa_g,
            xr, xw, xk, xv, xa, xg);
    }

    dim3 gBig(CC/128, BT/128);          // (16, 64)
    dim3 gSm(1, BT/64);                 // (1, 128)
    const unsigned SPLIT_BIG = (unsigned)(BTC/4/256);

    // 2. big projections (tensor cores, hi/lo split)
    split_kernel<<<SPLIT_BIG, 256>>>(xr, Abh, Abl, BTC/4);
    hgemm<0><<<gBig, 256, HSMEM>>>(Abh, Abl, Wr_h, Wr_l, r_, CC, CC, nullptr);
    split_kernel<<<SPLIT_BIG, 256>>>(xk, Abh, Abl, BTC/4);
    hgemm<0><<<gBig, 256, HSMEM>>>(Abh, Abl, Wk_h, Wk_l, k_, CC, CC, nullptr);
    split_kernel<<<SPLIT_BIG, 256>>>(xv, Abh, Abl, BTC/4);
    hgemm<0><<<gBig, 256, HSMEM>>>(Abh, Abl, Wv_h, Wv_l, vl, CC, CC, nullptr);

    // 3. LoRA stage-1 (SIMT fp32, fused activation)
    sgemm<64,64,16,4,4,1><<<gSm,256>>>(xw, td_w1, h_td, BT, 64, CC, nullptr);     // tanh
    sgemm<64,64,16,4,4,0><<<gSm,256>>>(xa, aaa_w1, h_aaa, BT, 64, CC, nullptr);
    sgemm<64,128,16,4,8,2><<<gSm,256>>>(xg, gate_w1, h_gate, BT, 128, CC, nullptr); // sigmoid
    sgemm<64,32,16,4,2,0><<<gSm,256>>>(xv, mv_w1, h_mv, BT, 32, CC, nullptr);

    // 3b. LoRA stage-2 (tensor cores, fused epilogues)
    split_kernel<<<(unsigned)(BT*64/4/256), 256>>>(h_td, td_h, td_l, (size_t)BT*64/4);
    hgemm<4><<<gBig, 256, HSMEM>>>(td_h, td_l, tdw_h, tdw_l, wd, 64, CC, time_decay);
    split_kernel<<<(unsigned)(BT*64/4/256), 256>>>(h_aaa, aaa_h, aaa_l, (size_t)BT*64/4);
    hgemm<3><<<gBig, 256, HSMEM>>>(aaa_h, aaa_l, aaaw_h, aaaw_l, a_, 64, CC, time_aaaaa);
    split_kernel<<<(unsigned)(BT*128/4/256), 256>>>(h_gate, gate_h, gate_l, (size_t)BT*128/4);
    hgemm<0><<<gBig, 256, HSMEM>>>(gate_h, gate_l, gatew_h, gatew_l, g_, 128, CC, nullptr);
    split_kernel<<<(unsigned)(BT*32/4/256), 256>>>(h_mv, mv_h, mv_l, (size_t)BT*32/4);
    hgemm<3><<<gBig, 256, HSMEM>>>(mv_h, mv_l, mvw_h, mvw_l, s_, 32, CC, misc_v);

    // 4. prep + transpose to head-major
    {
        int warps = BT * HH;
        prep_kernel<<<warps/8, 256>>>(r_, wd, k_, a_, vl, s_, v0,
                                      misc_kkk, misc_a,
                                      rT, wT, kT, vT, aT, bT);
    }

    // 5. WKV7 recurrence
    wkv7_kernel<<<BB*HH, 64>>>(rT, wT, kT, vT, aT, bT, yT);

    // 6. groupnorm + bonus + gate
    {
        int warps = BT * HH;
        post_kernel<<<warps/8, 256>>>(yT, rT, kT, vT, g_, faaaa, ln_w, ln_b, z_);
    }

    // 7. output projection (tensor cores) directly into d_out
    split_kernel<<<SPLIT_BIG, 256>>>(z_, Abh, Abl, BTC/4);
    hgemm<0><<<gBig, 256, HSMEM>>>(Abh, Abl, Wo_h, Wo_l, (float*)d_out, CC, CC, nullptr);

    // 8. second output: v0 passthrough
    if ((size_t)out_size >= 2 * BTC) {
        size_t n4 = BTC / 4;
        copy4_kernel<<<(unsigned)((n4 + 255) / 256), 256>>>(
            v0, (float*)d_out + BTC, n4);
    }
}

// round 5
// speedup vs baseline: 2.0059x; 1.1229x over previous
#include <cuda_runtime.h>
#include <cuda_bf16.h>
#include <math.h>
#include <stdint.h>

// ---------------------------------------------------------------------------
// RWKV-7 Tmix forward. B=4, T=2048, C=2048, H=32, N=64.
// R5: all GEMMs on tensor cores (mma.sync bf16 hi/lo split). Fused splits.
// WKV7 recurrence at 256 threads/block.
// ---------------------------------------------------------------------------

#define BB 4
#define TT 2048
#define CC 2048
#define HH 32
#define NN 64
#define BT (BB*TT)                       // 8192
#define BTC ((size_t)BT*(size_t)CC)      // 16777216

// Scratch pool: 23 BTC-sized fp32 slots.
__device__ float g_pool[23ull * 16777216ull];

// slots 0-5: mix outputs as bf16 hi/lo pairs (hi at 0, lo at +BTC bf16)
#define SL_XR 0
#define SL_XW 1
#define SL_XK 2
#define SL_XV 3
#define SL_XA 4
#define SL_XG 5
#define SL_R  6
#define SL_K  7
#define SL_VL 8
#define SL_G  9
#define SL_WD 10
#define SL_A  11
#define SL_S  12
#define SL_RT 13
#define SL_WT 14
#define SL_KT 15
#define SL_VT 16
#define SL_AT 17
#define SL_BT 18
#define SL_Y  19
#define SL_ZS 20     // z as bf16 hi/lo
#define SL_SMALL 21  // hcat h/l, W1cat h/l, stage-2 weight splits
#define SL_WB  22    // big weight bf16 splits: 8 x (2048*2048) bf16 = 1 slot

// ===========================================================================
// helpers
// ===========================================================================
__device__ __forceinline__ uint32_t smem_u32(const void* p) {
    uint32_t a;
    asm("{ .reg .u64 t; cvta.to.shared.u64 t, %1; cvt.u32.u64 %0, t; }"
        : "=r"(a) : "l"(p));
    return a;
}
__device__ __forceinline__ void cpasync16(uint32_t dst, const void* src) {
    asm volatile("cp.async.cg.shared.global [%0], [%1], 16;" :: "r"(dst), "l"(src));
}
__device__ __forceinline__ void ldsm4(uint32_t* r, uint32_t addr) {
    asm volatile("ldmatrix.sync.aligned.m8n8.x4.shared.b16 {%0,%1,%2,%3}, [%4];"
        : "=r"(r[0]), "=r"(r[1]), "=r"(r[2]), "=r"(r[3]) : "r"(addr));
}
__device__ __forceinline__ void mma16816(float* d, const uint32_t* a, const uint32_t* b) {
    asm volatile(
        "mma.sync.aligned.m16n8k16.row.col.f32.bf16.bf16.f32 "
        "{%0,%1,%2,%3}, {%4,%5,%6,%7}, {%8,%9}, {%0,%1,%2,%3};"
        : "+f"(d[0]), "+f"(d[1]), "+f"(d[2]), "+f"(d[3])
        : "r"(a[0]), "r"(a[1]), "r"(a[2]), "r"(a[3]), "r"(b[0]), "r"(b[1]));
}
__device__ __forceinline__ uint32_t pack_bf2(float a, float b) {
    __nv_bfloat162 t = __floats2bfloat162_rn(a, b);
    return *reinterpret_cast<uint32_t*>(&t);
}

// EPI: 0=none, 3=sigmoid(v+bias[n]), 4=decay transform with bias[n]
template<int EPI>
__device__ __forceinline__ float epi_apply(float v, float b) {
    if (EPI == 3) {
        return 1.f / (1.f + expf(-(v + b)));
    } else if (EPI == 4) {
        float z  = v + b;
        float sp = (z < -20.f) ? (-z) : log1pf(expf(-z));
        float w  = -sp - 0.5f;
        return expf(-expf(w));
    }
    return v;
}

// ===========================================================================
// Main tensor GEMM: C[M,Ntot] = (Ah+Al)[M,K(lda)] @ (Bh+Bl)[Ntot,K]^T
// D = Ah*Bh + Ah*Bl + Al*Bh, fp32 accum. CTA 128x128x32, 4-stage cp.async,
// warp tile 64x32 (2x4 warps).
// ===========================================================================
#define PADK 40
#define TILE_B (128*PADK*2)              // 10240 bytes per operand tile
#define STG_B  (4*TILE_B)                // 40960
#define HSTAGES 4
#define HSMEM  (HSTAGES*STG_B)           // 163840

template<int EPI>
__global__ void __launch_bounds__(256, 1)
hgemm(const __nv_bfloat16* __restrict__ Ah, const __nv_bfloat16* __restrict__ Al,
      const __nv_bfloat16* __restrict__ Bh, const __nv_bfloat16* __restrict__ Bl,
      float* __restrict__ C, int K, int lda, int Ntot, const float* __restrict__ bias)
{
    extern __shared__ char sm[];
    const int tid  = threadIdx.x;
    const int lane = tid & 31;
    const int wid  = tid >> 5;
    const int m0 = blockIdx.y * 128;
    const int n0 = blockIdx.x * 128;
    const int mw = (wid >> 2) * 64;
    const int nw = (wid & 3) * 32;
    const uint32_t sbase = smem_u32(sm);
    const int KT = K >> 5;

    float acc[4][4][4];
#pragma unroll
    for (int mt = 0; mt < 4; mt++)
#pragma unroll
        for (int nt = 0; nt < 4; nt++)
#pragma unroll
            for (int q = 0; q < 4; q++) acc[mt][nt][q] = 0.f;

    auto issue = [&](int kt, int stage) {
        const int k0 = kt << 5;
        const uint32_t sdst = sbase + stage * STG_B;
#pragma unroll
        for (int u = 0; u < 8; u++) {
            int i  = tid + u * 256;
            int op = i >> 9;
            int r  = (i & 511) >> 2;
            int c  = i & 3;
            const __nv_bfloat16* src;
            if (op == 0)      src = Ah + (size_t)(m0 + r) * lda + k0 + c * 8;
            else if (op == 1) src = Al + (size_t)(m0 + r) * lda + k0 + c * 8;
            else if (op == 2) src = Bh + (size_t)(n0 + r) * K + k0 + c * 8;
            else              src = Bl + (size_t)(n0 + r) * K + k0 + c * 8;
            cpasync16(sdst + op * TILE_B + r * (PADK*2) + c * 16, src);
        }
    };

#pragma unroll
    for (int s = 0; s < HSTAGES - 1; s++) {
        if (s < KT) issue(s, s);
        asm volatile("cp.async.commit_group;" ::: "memory");
    }

    const int grp = lane >> 3;
    const int l7  = lane & 7;

    for (int kt = 0; kt < KT; kt++) {
        asm volatile("cp.async.wait_group 2;" ::: "memory");
        __syncthreads();

        const int st = kt % HSTAGES;
        const uint32_t sAh = sbase + st * STG_B;
        const uint32_t sAl = sAh + TILE_B;
        const uint32_t sBh = sAh + 2 * TILE_B;
        const uint32_t sBl = sAh + 3 * TILE_B;

#pragma unroll
        for (int kk = 0; kk < 2; kk++) {
            const int ko = kk * 16;
            uint32_t ahf[4][4], alf[4][4], bhf[4][2], blf[4][2];
#pragma unroll
            for (int mt = 0; mt < 4; mt++) {
                int row = mw + mt * 16 + ((grp & 1) << 3) + l7;
                int kof = ko + ((grp & 2) << 2);
                uint32_t a = row * (PADK*2) + kof * 2;
                ldsm4(ahf[mt], sAh + a);
                ldsm4(alf[mt], sAl + a);
            }
#pragma unroll
            for (int np = 0; np < 2; np++) {
                int row = nw + np * 16 + ((grp >> 1) << 3) + l7;
                int kof = ko + ((grp & 1) << 3);
                uint32_t a = row * (PADK*2) + kof * 2;
                uint32_t t[4];
                ldsm4(t, sBh + a);
                bhf[np*2][0]   = t[0]; bhf[np*2][1]   = t[1];
                bhf[np*2+1][0] = t[2]; bhf[np*2+1][1] = t[3];
                ldsm4(t, sBl + a);
                blf[np*2][0]   = t[0]; blf[np*2][1]   = t[1];
                blf[np*2+1][0] = t[2]; blf[np*2+1][1] = t[3];
            }
#pragma unroll
            for (int mt = 0; mt < 4; mt++)
#pragma unroll
                for (int nt = 0; nt < 4; nt++) {
                    mma16816(acc[mt][nt], ahf[mt], bhf[nt]);
                    mma16816(acc[mt][nt], ahf[mt], blf[nt]);
                    mma16816(acc[mt][nt], alf[mt], bhf[nt]);
                }
        }

        int nkt = kt + HSTAGES - 1;
        if (nkt < KT) issue(nkt, nkt % HSTAGES);
        asm volatile("cp.async.commit_group;" ::: "memory");
    }

    const int r0 = lane >> 2;
    const int c0 = (lane & 3) * 2;
#pragma unroll
    for (int mt = 0; mt < 4; mt++) {
#pragma unroll
        for (int nt = 0; nt < 4; nt++) {
            int row = m0 + mw + mt * 16 + r0;
            int col = n0 + nw + nt * 8 + c0;
            float b0 = 0.f, b1 = 0.f;
            if (EPI != 0) { b0 = bias[col]; b1 = bias[col + 1]; }
            float v0 = epi_apply<EPI>(acc[mt][nt][0], b0);
            float v1 = epi_apply<EPI>(acc[mt][nt][1], b1);
            float v2 = epi_apply<EPI>(acc[mt][nt][2], b0);
            float v3 = epi_apply<EPI>(acc[mt][nt][3], b1);
            *(float2*)(C + (size_t)row * Ntot + col)       = make_float2(v0, v1);
            *(float2*)(C + (size_t)(row + 8) * Ntot + col) = make_float2(v2, v3);
        }
    }
}

// ===========================================================================
// Stage-1 fused LoRA GEMM: 5 column segments of W1cat[320][2048]:
//   seg0 [0,64)=td(tanh,A=xw)  seg1 [64,128)=aaa(none,A=xa)
//   seg2/3 [128,256)=gate(sigmoid,A=xg)  seg4 [256,320)=mv(none,A=xv)
// CTA 128x64x32, 3 stages. Output: bf16 hi/lo into hcat[8192][320].
// ===========================================================================
#define S1_ATILE (128*PADK*2)    // 10240
#define S1_BTILE (64*PADK*2)     // 5120
#define S1_STG   (2*S1_ATILE + 2*S1_BTILE)   // 30720
#define S1_SMEM  (3*S1_STG)                  // 92160
#define HCATN 320

__global__ void __launch_bounds__(256, 1)
hgemm_s1(const __nv_bfloat16* __restrict__ xw_h, const __nv_bfloat16* __restrict__ xw_l,
         const __nv_bfloat16* __restrict__ xa_h, const __nv_bfloat16* __restrict__ xa_l,
         const __nv_bfloat16* __restrict__ xg_h, const __nv_bfloat16* __restrict__ xg_l,
         const __nv_bfloat16* __restrict__ xv_h, const __nv_bfloat16* __restrict__ xv_l,
         const __nv_bfloat16* __restrict__ W1h, const __nv_bfloat16* __restrict__ W1l,
         __nv_bfloat16* __restrict__ Hh, __nv_bfloat16* __restrict__ Hl)
{
    extern __shared__ char sm[];
    const int tid  = threadIdx.x;
    const int lane = tid & 31;
    const int wid  = tid >> 5;
    const int seg  = blockIdx.x;               // 0..4
    const int m0   = blockIdx.y * 128;
    const int n0w  = seg * 64;                 // row base in W1cat
    const uint32_t sbase = smem_u32(sm);

    const __nv_bfloat16* Ah;
    const __nv_bfloat16* Al;
    if (seg == 0)      { Ah = xw_h; Al = xw_l; }
    else if (seg == 1) { Ah = xa_h; Al = xa_l; }
    else if (seg <= 3) { Ah = xg_h; Al = xg_l; }
    else               { Ah = xv_h; Al = xv_l; }

    const int mw = (wid >> 1) * 32;            // 4 warps in m
    const int nw = (wid & 1) * 32;             // 2 warps in n

    float acc[2][4][4];
#pragma unroll
    for (int mt = 0; mt < 2; mt++)
#pragma unroll
        for (int nt = 0; nt < 4; nt++)
#pragma unroll
            for (int q = 0; q < 4; q++) acc[mt][nt][q] = 0.f;

    auto issue = [&](int kt, int stage) {
        const int k0 = kt << 5;
        const uint32_t sdst = sbase + stage * S1_STG;
#pragma unroll
        for (int u = 0; u < 6; u++) {
            int i = tid + u * 256;
            if (i < 1024) {
                int sp = i >> 9, r = (i >> 2) & 127, c = i & 3;
                const __nv_bfloat16* src = (sp ? Al : Ah) + (size_t)(m0 + r) * CC + k0 + c * 8;
                cpasync16(sdst + sp * S1_ATILE + r * (PADK*2) + c * 16, src);
            } else {
                int j = i - 1024;
                int sp = j >> 8, r = (j >> 2) & 63, c = j & 3;
                const __nv_bfloat16* src = (sp ? W1l : W1h) + (size_t)(n0w + r) * CC + k0 + c * 8;
                cpasync16(sdst + 2*S1_ATILE + sp * S1_BTILE + r * (PADK*2) + c * 16, src);
            }
        }
    };

#pragma unroll
    for (int s = 0; s < 2; s++) {
        issue(s, s);
        asm volatile("cp.async.commit_group;" ::: "memory");
    }

    const int grp = lane >> 3;
    const int l7  = lane & 7;
    const int KT = CC >> 5;   // 64

    for (int kt = 0; kt < KT; kt++) {
        asm volatile("cp.async.wait_group 1;" ::: "memory");
        __syncthreads();

        const int st = kt % 3;
        const uint32_t sAh = sbase + st * S1_STG;
        const uint32_t sAl = sAh + S1_ATILE;
        const uint32_t sBh = sAh + 2 * S1_ATILE;
        const uint32_t sBl = sBh + S1_BTILE;

#pragma unroll
        for (int kk = 0; kk < 2; kk++) {
            const int ko = kk * 16;
            uint32_t ahf[2][4], alf[2][4], bhf[4][2], blf[4][2];
#pragma unroll
            for (int mt = 0; mt < 2; mt++) {
                int row = mw + mt * 16 + ((grp & 1) << 3) + l7;
                int kof = ko + ((grp & 2) << 2);
                uint32_t a = row * (PADK*2) + kof * 2;
                ldsm4(ahf[mt], sAh + a);
                ldsm4(alf[mt], sAl + a);
            }
#pragma unroll
            for (int np = 0; np < 2; np++) {
                int row = nw + np * 16 + ((grp >> 1) << 3) + l7;
                int kof = ko + ((grp & 1) << 3);
                uint32_t a = row * (PADK*2) + kof * 2;
                uint32_t t[4];
                ldsm4(t, sBh + a);
                bhf[np*2][0]   = t[0]; bhf[np*2][1]   = t[1];
                bhf[np*2+1][0] = t[2]; bhf[np*2+1][1] = t[3];
                ldsm4(t, sBl + a);
                blf[np*2][0]   = t[0]; blf[np*2][1]   = t[1];
                blf[np*2+1][0] = t[2]; blf[np*2+1][1] = t[3];
            }
#pragma unroll
            for (int mt = 0; mt < 2; mt++)
#pragma unroll
                for (int nt = 0; nt < 4; nt++) {
                    mma16816(acc[mt][nt], ahf[mt], bhf[nt]);
                    mma16816(acc[mt][nt], ahf[mt], blf[nt]);
                    mma16816(acc[mt][nt], alf[mt], bhf[nt]);
                }
        }

        int nkt = kt + 2;
        if (nkt < KT) issue(nkt, nkt % 3);
        asm volatile("cp.async.commit_group;" ::: "memory");
    }

    // epilogue: activation by segment, split to bf16 hi/lo into hcat
    const int r0 = lane >> 2;
    const int c0 = (lane & 3) * 2;
#pragma unroll
    for (int mt = 0; mt < 2; mt++) {
#pragma unroll
        for (int nt = 0; nt < 4; nt++) {
            float v[4];
#pragma unroll
            for (int q = 0; q < 4; q++) {
                float t = acc[mt][nt][q];
                if (seg == 0)              t = tanhf(t);
                else if (seg == 2 || seg == 3) t = 1.f / (1.f + expf(-t));
                v[q] = t;
            }
            int row = m0 + mw + mt * 16 + r0;
            int col = seg * 64 + nw + nt * 8 + c0;
            float h0 = __bfloat162float(__float2bfloat16(v[0]));
            float h1 = __bfloat162float(__float2bfloat16(v[1]));
            float h2 = __bfloat162float(__float2bfloat16(v[2]));
            float h3 = __bfloat162float(__float2bfloat16(v[3]));
            *(uint32_t*)&Hh[(size_t)row * HCATN + col]       = pack_bf2(v[0], v[1]);
            *(uint32_t*)&Hl[(size_t)row * HCATN + col]       = pack_bf2(v[0]-h0, v[1]-h1);
            *(uint32_t*)&Hh[(size_t)(row+8) * HCATN + col]   = pack_bf2(v[2], v[3]);
            *(uint32_t*)&Hl[(size_t)(row+8) * HCATN + col]   = pack_bf2(v[2]-h2, v[3]-h3);
        }
    }
}

// ===========================================================================
// Weight transpose + split: W[K][N] fp32 -> Th/Tl[N][K] bf16
// ===========================================================================
__global__ void transpose_split(const float* __restrict__ W,
                                __nv_bfloat16* __restrict__ Th,
                                __nv_bfloat16* __restrict__ Tl, int K, int N)
{
    __shared__ float tile[32][33];
    int bx = blockIdx.x * 32;   // n
    int by = blockIdx.y * 32;   // k
#pragma unroll
    for (int j = 0; j < 32; j += 8)
        tile[threadIdx.y + j][threadIdx.x] =
            W[(size_t)(by + threadIdx.y + j) * N + bx + threadIdx.x];
    __syncthreads();
#pragma unroll
    for (int j = 0; j < 32; j += 8) {
        float v = tile[threadIdx.x][threadIdx.y + j];
        int n = bx + threadIdx.y + j;
        int k = by + threadIdx.x;
        __nv_bfloat16 h = __float2bfloat16(v);
        Th[(size_t)n * K + k] = h;
        Tl[(size_t)n * K + k] = __float2bfloat16(v - __bfloat162float(h));
    }
}

// ---------------------------------------------------------------------------
// Token-shift mixing, fused bf16 hi/lo split output for all 6 streams.
// ---------------------------------------------------------------------------
__global__ void mix_split_kernel(const float* __restrict__ x,
    const float* __restrict__ mr, const float* __restrict__ mw,
    const float* __restrict__ mk, const float* __restrict__ mv,
    const float* __restrict__ ma, const float* __restrict__ mg,
    __nv_bfloat16* __restrict__ rh, __nv_bfloat16* __restrict__ rl,
    __nv_bfloat16* __restrict__ wh, __nv_bfloat16* __restrict__ wl,
    __nv_bfloat16* __restrict__ kh, __nv_bfloat16* __restrict__ kl,
    __nv_bfloat16* __restrict__ vh, __nv_bfloat16* __restrict__ vl,
    __nv_bfloat16* __restrict__ ah, __nv_bfloat16* __restrict__ al,
    __nv_bfloat16* __restrict__ gh, __nv_bfloat16* __restrict__ gl)
{
    size_t i = (size_t)blockIdx.x * blockDim.x + threadIdx.x;
    size_t n4 = BTC / 4;
    if (i >= n4) return;
    size_t e = i * 4;
    int c  = (int)(e % CC);
    int bt = (int)(e / CC);
    int t  = bt % TT;

    float4 xc = ((const float4*)x)[i];
    float4 xp = make_float4(0.f, 0.f, 0.f, 0.f);
    if (t > 0) xp = ((const float4*)x)[i - CC/4];
    float4 xx = make_float4(xp.x-xc.x, xp.y-xc.y, xp.z-xc.z, xp.w-xc.w);

    int c4 = c / 4;
#define DOMIX(MV, OH, OL) { \
        float4 m = ((const float4*)MV)[c4]; \
        float4 o = make_float4(xc.x + xx.x*m.x, xc.y + xx.y*m.y, \
                               xc.z + xx.z*m.z, xc.w + xx.w*m.w); \
        float h0 = __bfloat162float(__float2bfloat16(o.x)); \
        float h1 = __bfloat162float(__float2bfloat16(o.y)); \
        float h2 = __bfloat162float(__float2bfloat16(o.z)); \
        float h3 = __bfloat162float(__float2bfloat16(o.w)); \
        ((uint2*)OH)[i] = make_uint2(pack_bf2(o.x, o.y), pack_bf2(o.z, o.w)); \
        ((uint2*)OL)[i] = make_uint2(pack_bf2(o.x-h0, o.y-h1), pack_bf2(o.z-h2, o.w-h3)); }
    DOMIX(mr, rh, rl); DOMIX(mw, wh, wl); DOMIX(mk, kh, kl);
    DOMIX(mv, vh, vl); DOMIX(ma, ah, al); DOMIX(mg, gh, gl);
#undef DOMIX
}

// ---------------------------------------------------------------------------
__device__ __forceinline__ float warp_sum(float v) {
#pragma unroll
    for (int o = 16; o > 0; o >>= 1) v += __shfl_xor_sync(0xffffffffu, v, o);
    return v;
}

// ---------------------------------------------------------------------------
// Prep: value-residual mix, kk normalize, k adjust, transpose to [B*H, T, N].
// ---------------------------------------------------------------------------
__global__ void prep_kernel(const float* __restrict__ r,  const float* __restrict__ wd,
                            const float* __restrict__ k,  const float* __restrict__ a,
                            const float* __restrict__ vl, const float* __restrict__ s,
                            const float* __restrict__ v0,
                            const float* __restrict__ misc_kkk,
                            const float* __restrict__ misc_a,
                            float* __restrict__ rT, float* __restrict__ wT,
                            float* __restrict__ kT, float* __restrict__ vT,
                            float* __restrict__ aT, float* __restrict__ bT)
{
    int gw   = (blockIdx.x * blockDim.x + threadIdx.x) >> 5;
    int lane = threadIdx.x & 31;
    if (gw >= BT * HH) return;
    int h  = gw % HH;
    int bt = gw / HH;
    int b  = bt / TT, t = bt % TT;

    size_t src = (size_t)bt * CC + (size_t)h * NN;
    size_t dst = (((size_t)(b*HH + h)) * TT + t) * NN;
    int n0 = lane, n1 = lane + 32;
    int c0 = h*NN + n0, c1 = h*NN + n1;

    float k0 = k[src+n0], k1 = k[src+n1];
    float kk0 = k0 * misc_kkk[c0], kk1 = k1 * misc_kkk[c1];
    float ssq = warp_sum(kk0*kk0 + kk1*kk1);
    float inv = 1.f / fmaxf(sqrtf(ssq), 1e-12f);
    kk0 *= inv; kk1 *= inv;

    float a0 = a[src+n0], a1 = a[src+n1];
    float vv0 = vl[src+n0], vv1 = vl[src+n1];
    float s0 = s[src+n0], s1 = s[src+n1];
    float fv0 = vv0 + (v0[src+n0] - vv0) * s0;
    float fv1 = vv1 + (v0[src+n1] - vv1) * s1;
    float fk0 = k0 * (1.f + (a0 - 1.f) * misc_a[c0]);
    float fk1 = k1 * (1.f + (a1 - 1.f) * misc_a[c1]);

    rT[dst+n0] = r[src+n0];  rT[dst+n1] = r[src+n1];
    wT[dst+n0] = wd[src+n0]; wT[dst+n1] = wd[src+n1];
    kT[dst+n0] = fk0;        kT[dst+n1] = fk1;
    vT[dst+n0] = fv0;        vT[dst+n1] = fv1;
    aT[dst+n0] = -kk0;       aT[dst+n1] = -kk1;
    bT[dst+n0] = kk0*a0;     bT[dst+n1] = kk1*a1;
}

// ---------------------------------------------------------------------------
// WKV7 recurrence: 256 threads/block. Thread (row=tid>>2, cg=tid&3) owns
// S[row][cg*16 .. cg*16+15]. sai / y reduced via shfl within quads.
// ---------------------------------------------------------------------------
__global__ void __launch_bounds__(256)
wkv7_kernel(const float* __restrict__ rT, const float* __restrict__ wT,
            const float* __restrict__ kT, const float* __restrict__ vT,
            const float* __restrict__ aT, const float* __restrict__ bT,
            float* __restrict__ yT)
{
    __shared__ __align__(16) float sb[2][6][NN];
    const int bh  = blockIdx.x;
    const int tid = threadIdx.x;
    const int row = tid >> 2;
    const int cg  = tid & 3;
    const int cb  = cg * 16;
    const size_t gbase = (size_t)bh * TT * NN;

    // prefetch source pointers (arrays: 0=r 1=w 2=k 3=v 4=a 5=b)
    int a0 = tid >> 6;
    const float* p0 = (a0 == 0 ? rT : a0 == 1 ? wT : a0 == 2 ? kT : vT)
                      + gbase + (tid & 63);
    const float* p1 = ((tid >> 6) == 0 ? aT : bT) + gbase + (tid & 63);
    float* sbf = &sb[0][0][0];
    const int off0 = tid;            // arrays 0..3 flattened: a0*64 + (tid&63) = tid
    const int off1 = 256 + tid;      // arrays 4,5 (tid<128)

    float st[16];
#pragma unroll
    for (int j = 0; j < 16; j++) st[j] = 0.f;

    // preload t=0
    sbf[off0] = p0[0];
    if (tid < 128) sbf[off1] = p1[0];
    __syncthreads();

    int cur = 0;
    for (int t = 0; t < TT; t++) {
        float pf0 = 0.f, pf1 = 0.f;
        if (t + 1 < TT) {
            size_t o = (size_t)(t + 1) * NN;
            pf0 = p0[o];
            if (tid < 128) pf1 = p1[o];
        }

        const float* base = &sb[cur][0][0];
        const float4* r4p = (const float4*)(base + 0*NN + cb);
        const float4* w4p = (const float4*)(base + 1*NN + cb);
        const float4* k4p = (const float4*)(base + 2*NN + cb);
        const float4* a4p = (const float4*)(base + 4*NN + cb);
        const float4* b4p = (const float4*)(base + 5*NN + cb);
        const float vi = base[3*NN + row];

        // sa partial over 16 cols
        float c0=0.f, c1=0.f, c2=0.f, c3=0.f;
#pragma unroll
        for (int q = 0; q < 4; q++) {
            float4 a4 = a4p[q];
            c0 = fmaf(st[q*4+0], a4.x, c0);
            c1 = fmaf(st[q*4+1], a4.y, c1);
            c2 = fmaf(st[q*4+2], a4.z, c2);
            c3 = fmaf(st[q*4+3], a4.w, c3);
        }
        float sai = (c0 + c1) + (c2 + c3);
        sai += __shfl_xor_sync(0xffffffffu, sai, 1);
        sai += __shfl_xor_sync(0xffffffffu, sai, 2);

        // update + y partial
        float y0=0.f, y1=0.f, y2=0.f, y3=0.f;
#pragma unroll
        for (int q = 0; q < 4; q++) {
            float4 w4 = w4p[q], b4 = b4p[q], k4 = k4p[q], r4 = r4p[q];
            float t0 = fmaf(sai, b4.x, fmaf(vi, k4.x, st[q*4+0]*w4.x));
            float t1 = fmaf(sai, b4.y, fmaf(vi, k4.y, st[q*4+1]*w4.y));
            float t2 = fmaf(sai, b4.z, fmaf(vi, k4.z, st[q*4+2]*w4.z));
            float t3 = fmaf(sai, b4.w, fmaf(vi, k4.w, st[q*4+3]*w4.w));
            st[q*4+0] = t0; st[q*4+1] = t1; st[q*4+2] = t2; st[q*4+3] = t3;
            y0 = fmaf(t0, r4.x, y0);
            y1 = fmaf(t1, r4.y, y1);
            y2 = fmaf(t2, r4.z, y2);
            y3 = fmaf(t3, r4.w, y3);
        }
        float yp = (y0 + y1) + (y2 + y3);
        yp += __shfl_xor_sync(0xffffffffu, yp, 1);
        yp += __shfl_xor_sync(0xffffffffu, yp, 2);
        if (cg == 0) yT[gbase + (size_t)t * NN + row] = yp;

        int nxt = cur ^ 1;
        if (t + 1 < TT) {
            sbf[nxt*384 + off0] = pf0;
            if (tid < 128) sbf[nxt*384 + off1] = pf1;
        }
        __syncthreads();
        cur = nxt;
    }
}

// ---------------------------------------------------------------------------
// GroupNorm + bonus + gate. Output z as bf16 hi/lo (GEMM A operand).
// ---------------------------------------------------------------------------
__global__ void post_kernel(const float* __restrict__ yT, const float* __restrict__ rT,
                            const float* __restrict__ kT, const float* __restrict__ vT,
                            const float* __restrict__ g,  const float* __restrict__ faaaa,
                            const float* __restrict__ lnw, const float* __restrict__ lnb,
                            __nv_bfloat16* __restrict__ zh, __nv_bfloat16* __restrict__ zl)
{
    int gw   = (blockIdx.x * blockDim.x + threadIdx.x) >> 5;
    int lane = threadIdx.x & 31;
    if (gw >= BT * HH) return;
    int h  = gw % HH;
    int bt = gw / HH;
    int b  = bt / TT, t = bt % TT;

    size_t src = (size_t)bt * CC + (size_t)h * NN;
    size_t dst = (((size_t)(b*HH + h)) * TT + t) * NN;
    int n0 = lane, n1 = lane + 32;
    int c0 = h*NN + n0, c1 = h*NN + n1;

    float y0 = yT[dst+n0], y1 = yT[dst+n1];
    float sum = warp_sum(y0 + y1);
    float sq  = warp_sum(y0*y0 + y1*y1);
    float mu  = sum * (1.f/64.f);
    float var = sq * (1.f/64.f) - mu*mu;
    float rs  = rsqrtf(var + 6.4e-4f);

    float rk = rT[dst+n0]*kT[dst+n0]*faaaa[c0]
             + rT[dst+n1]*kT[dst+n1]*faaaa[c1];
    float srk = warp_sum(rk);

    float z0 = ((y0 - mu)*rs*lnw[c0] + lnb[c0] + srk*vT[dst+n0]) * g[src+n0];
    float z1 = ((y1 - mu)*rs*lnw[c1] + lnb[c1] + srk*vT[dst+n1]) * g[src+n1];
    __nv_bfloat16 h0 = __float2bfloat16(z0);
    __nv_bfloat16 h1 = __float2bfloat16(z1);
    zh[src+n0] = h0; zh[src+n1] = h1;
    zl[src+n0] = __float2bfloat16(z0 - __bfloat162float(h0));
    zl[src+n1] = __float2bfloat16(z1 - __bfloat162float(h1));
}

__global__ void copy4_kernel(const float* __restrict__ src, float* __restrict__ dst,
                             size_t n4)
{
    size_t i = (size_t)blockIdx.x * blockDim.x + threadIdx.x;
    if (i < n4) ((float4*)dst)[i] = ((const float4*)src)[i];
}

// ---------------------------------------------------------------------------
// launch
// ---------------------------------------------------------------------------
extern "C" void kernel_launch(void* const* d_in, const int* in_sizes, int n_in,
                              void* d_out, int out_size)
{
    const float* x         = (const float*)d_in[0];
    const float* v0        = (const float*)d_in[1];
    const float* maa_r     = (const float*)d_in[2];
    const float* maa_w     = (const float*)d_in[3];
    const float* maa_k     = (const float*)d_in[4];
    const float* maa_v     = (const float*)d_in[5];
    const float* maa_a     = (const float*)d_in[6];
    const float* maa_g     = (const float*)d_in[7];
    const float* time_decay= (const float*)d_in[8];
    const float* faaaa     = (const float*)d_in[9];
    const float* time_aaaaa= (const float*)d_in[10];
    const float* td_w1     = (const float*)d_in[11];
    const float* td_w2     = (const float*)d_in[12];
    const float* aaa_w1    = (const float*)d_in[13];
    const float* aaa_w2    = (const float*)d_in[14];
    const float* gate_w1   = (const float*)d_in[15];
    const float* gate_w2   = (const float*)d_in[16];
    const float* mv_w1     = (const float*)d_in[17];
    const float* mv_w2     = (const float*)d_in[18];
    const float* misc_v    = (const float*)d_in[19];
    const float* misc_kkk  = (const float*)d_in[20];
    const float* misc_a    = (const float*)d_in[21];
    const float* Wr        = (const float*)d_in[22];
    const float* Wk        = (const float*)d_in[23];
    const float* Wv        = (const float*)d_in[24];
    const float* Wo        = (const float*)d_in[25];
    const float* ln_w      = (const float*)d_in[26];
    const float* ln_b      = (const float*)d_in[27];

    float* pool = nullptr;
    cudaGetSymbolAddress((void**)&pool, g_pool);

    // mix split slots
    __nv_bfloat16* xr_h = (__nv_bfloat16*)(pool + (size_t)SL_XR * BTC);
    __nv_bfloat16* xr_l = xr_h + BTC;
    __nv_bfloat16* xw_h = (__nv_bfloat16*)(pool + (size_t)SL_XW * BTC);
    __nv_bfloat16* xw_l = xw_h + BTC;
    __nv_bfloat16* xk_h = (__nv_bfloat16*)(pool + (size_t)SL_XK * BTC);
    __nv_bfloat16* xk_l = xk_h + BTC;
    __nv_bfloat16* xv_h = (__nv_bfloat16*)(pool + (size_t)SL_XV * BTC);
    __nv_bfloat16* xv_l = xv_h + BTC;
    __nv_bfloat16* xa_h = (__nv_bfloat16*)(pool + (size_t)SL_XA * BTC);
    __nv_bfloat16* xa_l = xa_h + BTC;
    __nv_bfloat16* xg_h = (__nv_bfloat16*)(pool + (size_t)SL_XG * BTC);
    __nv_bfloat16* xg_l = xg_h + BTC;

    float* r_ = pool + (size_t)SL_R  * BTC;
    float* k_ = pool + (size_t)SL_K  * BTC;
    float* vl = pool + (size_t)SL_VL * BTC;
    float* g_ = pool + (size_t)SL_G  * BTC;
    float* wd = pool + (size_t)SL_WD * BTC;
    float* a_ = pool + (size_t)SL_A  * BTC;
    float* s_ = pool + (size_t)SL_S  * BTC;
    float* rT = pool + (size_t)SL_RT * BTC;
    float* wT = pool + (size_t)SL_WT * BTC;
    float* kT = pool + (size_t)SL_KT * BTC;
    float* vT = pool + (size_t)SL_VT * BTC;
    float* aT = pool + (size_t)SL_AT * BTC;
    float* bT = pool + (size_t)SL_BT * BTC;
    float* yT = pool + (size_t)SL_Y  * BTC;
    __nv_bfloat16* z_h = (__nv_bfloat16*)(pool + (size_t)SL_ZS * BTC);
    __nv_bfloat16* z_l = z_h + BTC;

    // SMALL slot: hcat splits, W1cat splits, stage-2 weight splits
    __nv_bfloat16* sb16 = (__nv_bfloat16*)(pool + (size_t)SL_SMALL * BTC);
    __nv_bfloat16* hcat_h = sb16;                                 // 8192*320
    __nv_bfloat16* hcat_l = hcat_h + (size_t)BT * HCATN;
    __nv_bfloat16* W1h    = hcat_l + (size_t)BT * HCATN;          // 320*2048
    __nv_bfloat16* W1l    = W1h + (size_t)HCATN * CC;
    __nv_bfloat16* tdw_h  = W1l + (size_t)HCATN * CC;             // 2048*64
    __nv_bfloat16* tdw_l  = tdw_h  + (size_t)CC * 64;
    __nv_bfloat16* aaaw_h = tdw_l  + (size_t)CC * 64;
    __nv_bfloat16* aaaw_l = aaaw_h + (size_t)CC * 64;
    __nv_bfloat16* gatew_h= aaaw_l + (size_t)CC * 64;             // 2048*128
    __nv_bfloat16* gatew_l= gatew_h+ (size_t)CC * 128;
    __nv_bfloat16* mvw_h  = gatew_l+ (size_t)CC * 128;            // 2048*32
    __nv_bfloat16* mvw_l  = mvw_h  + (size_t)CC * 32;

    // big weight splits (exactly one slot: 8 * 2048*2048 bf16)
    __nv_bfloat16* wb = (__nv_bfloat16*)(pool + (size_t)SL_WB * BTC);
    const size_t WSZ = (size_t)CC * CC;
    __nv_bfloat16* Wr_h = wb;            __nv_bfloat16* Wr_l = wb + WSZ;
    __nv_bfloat16* Wk_h = wb + 2*WSZ;    __nv_bfloat16* Wk_l = wb + 3*WSZ;
    __nv_bfloat16* Wv_h = wb + 4*WSZ;    __nv_bfloat16* Wv_l = wb + 5*WSZ;
    __nv_bfloat16* Wo_h = wb + 6*WSZ;    __nv_bfloat16* Wo_l = wb + 7*WSZ;

    cudaFuncSetAttribute(hgemm<0>, cudaFuncAttributeMaxDynamicSharedMemorySize, HSMEM);
    cudaFuncSetAttribute(hgemm<3>, cudaFuncAttributeMaxDynamicSharedMemorySize, HSMEM);
    cudaFuncSetAttribute(hgemm<4>, cudaFuncAttributeMaxDynamicSharedMemorySize, HSMEM);
    cudaFuncSetAttribute(hgemm_s1, cudaFuncAttributeMaxDynamicSharedMemorySize, S1_SMEM);

    dim3 tb(32, 8);
    // 0. weight transpose + split
    transpose_split<<<dim3(CC/32, CC/32), tb>>>(Wr, Wr_h, Wr_l, CC, CC);
    transpose_split<<<dim3(CC/32, CC/32), tb>>>(Wk, Wk_h, Wk_l, CC, CC);
    transpose_split<<<dim3(CC/32, CC/32), tb>>>(Wv, Wv_h, Wv_l, CC, CC);
    transpose_split<<<dim3(CC/32, CC/32), tb>>>(Wo, Wo_h, Wo_l, CC, CC);
    // stage-1 weights into W1cat rows [0,64) td, [64,128) aaa, [128,256) gate, [256,288) mv
    transpose_split<<<dim3(64/32,  CC/32), tb>>>(td_w1,   W1h,                 W1l,                 CC, 64);
    transpose_split<<<dim3(64/32,  CC/32), tb>>>(aaa_w1,  W1h + (size_t)64*CC, W1l + (size_t)64*CC, CC, 64);
    transpose_split<<<dim3(128/32, CC/32), tb>>>(gate_w1, W1h + (size_t)128*CC,W1l + (size_t)128*CC,CC, 128);
    transpose_split<<<dim3(32/32,  CC/32), tb>>>(mv_w1,   W1h + (size_t)256*CC,W1l + (size_t)256*CC,CC, 32);
    // stage-2 weights
    transpose_split<<<dim3(CC/32, 64/32),  tb>>>(td_w2,  tdw_h,  tdw_l,  64,  CC);
    transpose_split<<<dim3(CC/32, 64/32),  tb>>>(aaa_w2, aaaw_h, aaaw_l, 64,  CC);
    transpose_split<<<dim3(CC/32, 128/32), tb>>>(gate_w2,gatew_h,gatew_l,128, CC);
    transpose_split<<<dim3(CC/32, 32/32),  tb>>>(mv_w2,  mvw_h,  mvw_l,  32,  CC);

    // 1. token-shift mixing + split
    {
        size_t n4 = BTC / 4;
        mix_split_kernel<<<(unsigned)((n4 + 255) / 256), 256>>>(
            x, maa_r, maa_w, maa_k, maa_v, maa_a, maa_g,
            xr_h, xr_l, xw_h, xw_l, xk_h, xk_l, xv_h, xv_l, xa_h, xa_l, xg_h, xg_l);
    }

    dim3 gBig(CC/128, BT/128);          // (16, 64)

    // 2. big projections
    hgemm<0><<<gBig, 256, HSMEM>>>(xr_h, xr_l, Wr_h, Wr_l, r_, CC, CC, CC, nullptr);
    hgemm<0><<<gBig, 256, HSMEM>>>(xk_h, xk_l, Wk_h, Wk_l, k_, CC, CC, CC, nullptr);
    hgemm<0><<<gBig, 256, HSMEM>>>(xv_h, xv_l, Wv_h, Wv_l, vl, CC, CC, CC, nullptr);

    // 3. stage-1 fused LoRA GEMM (tensor cores, split output)
    hgemm_s1<<<dim3(5, BT/128), 256, S1_SMEM>>>(
        xw_h, xw_l, xa_h, xa_l, xg_h, xg_l, xv_h, xv_l, W1h, W1l, hcat_h, hcat_l);

    // 3b. stage-2 (tensor cores, fused epilogues); A = hcat slices, lda=320
    hgemm<4><<<gBig, 256, HSMEM>>>(hcat_h,     hcat_l,     tdw_h,  tdw_l,  wd, 64,  HCATN, CC, time_decay);
    hgemm<3><<<gBig, 256, HSMEM>>>(hcat_h+64,  hcat_l+64,  aaaw_h, aaaw_l, a_, 64,  HCATN, CC, time_aaaaa);
    hgemm<0><<<gBig, 256, HSMEM>>>(hcat_h+128, hcat_l+128, gatew_h,gatew_l,g_, 128, HCATN, CC, nullptr);
    hgemm<3><<<gBig, 256, HSMEM>>>(hcat_h+256, hcat_l+256, mvw_h,  mvw_l,  s_, 32,  HCATN, CC, misc_v);

    // 4. prep + transpose to head-major
    {
        int warps = BT * HH;
        prep_kernel<<<warps/8, 256>>>(r_, wd, k_, a_, vl, s_, v0,
                                      misc_kkk, misc_a,
                                      rT, wT, kT, vT, aT, bT);
    }

    // 5. WKV7 recurrence (256 threads/block)
    wkv7_kernel<<<BB*HH, 256>>>(rT, wT, kT, vT, aT, bT, yT);

    // 6. groupnorm + bonus + gate -> z split
    {
        int warps = BT * HH;
        post_kernel<<<warps/8, 256>>>(yT, rT, kT, vT, g_, faaaa, ln_w, ln_b, z_h, z_l);
    }

    // 7. output projection directly into d_out
    hgemm<0><<<gBig, 256, HSMEM>>>(z_h, z_l, Wo_h, Wo_l, (float*)d_out, CC, CC, CC, nullptr);

    // 8. second output: v0 passthrough
    if ((size_t)out_size >= 2 * BTC) {
        size_t n4 = BTC / 4;
        copy4_kernel<<<(unsigned)((n4 + 255) / 256), 256>>>(
            v0, (float*)d_out + BTC, n4);
    }
}